// round 1
// baseline (speedup 1.0000x reference)
#include <cuda_runtime.h>
#include <cstdint>

#define BATCH 4
#define SEQ   2048
#define EMB   1024
#define HEADS 16
#define DK    64

// Scratch (no cudaMalloc allowed): qkv in [B,H,S,DK], attention out in [B,S,EMB]
__device__ float g_qkv[(size_t)BATCH * HEADS * SEQ * DK];
__device__ float g_att[(size_t)BATCH * SEQ * EMB];

// ---------------------------------------------------------------------------
// exp(s * 0.125) via exp2 polynomial on the FMA pipe (avoids MUFU bottleneck).
// s in [-64, 64] scaled -> t in [-11.6, 11.6]. Magic-constant round-to-nearest,
// degree-5 poly for 2^f on [-0.5, 0.5], exponent add. Rel err ~2e-6.
// ---------------------------------------------------------------------------
__device__ __forceinline__ float exp_scaled(float s) {
    const float C = 0.18033688011f;           // 0.125 * log2(e)
    float t = s * C;
    float z = t + 12582912.0f;                // 1.5 * 2^23 magic
    int   i = __float_as_int(z);              // low bits = round(t) (two's complement)
    float fi = z - 12582912.0f;
    float f = t - fi;                          // f in [-0.5, 0.5]
    float p = 1.33335581e-3f;
    p = fmaf(p, f, 9.61812910e-3f);
    p = fmaf(p, f, 5.55041087e-2f);
    p = fmaf(p, f, 2.40226512e-1f);
    p = fmaf(p, f, 6.93147182e-1f);
    p = fmaf(p, f, 1.0f);
    return __int_as_float(__float_as_int(p) + (i << 23));   // p * 2^round(t)
}

// ---------------------------------------------------------------------------
// Stage 1: qkv[b,h,s,d] = cos(x[b,s,h*64+d] + theta[h,d])
// ---------------------------------------------------------------------------
__global__ __launch_bounds__(256) void qkv_kernel(const float* __restrict__ x,
                                                  const float* __restrict__ theta) {
    int idx = blockIdx.x * 256 + threadIdx.x;            // over B*S*E
    int e = idx & (EMB - 1);
    int s = (idx >> 10) & (SEQ - 1);
    int b = idx >> 21;
    int h = e >> 6, d = e & (DK - 1);
    float v = cosf(x[idx] + theta[h * DK + d]);
    g_qkv[((((size_t)b * HEADS + h) * SEQ) + s) * DK + d] = v;
}

// ---------------------------------------------------------------------------
// Stage 2: single-pass attention (Q==K==V, scores bounded by 8 -> no max pass).
// 1 thread = 1 q row. q row (64f) + accumulator (64f) in registers.
// K tiles of 64 rows staged in shared memory, broadcast float4 reads.
// ---------------------------------------------------------------------------
__global__ __launch_bounds__(128) void attn_kernel() {
    int bid = blockIdx.x;                 // B*H*(S/128) = 1024 blocks
    int qt = bid & 15;                    // S / 128 = 16 q-tiles
    int bh = bid >> 4;
    int b = bh >> 4, h = bh & 15;

    const float* __restrict__ base = g_qkv + (size_t)bh * SEQ * DK;
    int q = qt * 128 + threadIdx.x;

    float qr[DK];
    #pragma unroll
    for (int i = 0; i < 16; i++) {
        float4 v = *(const float4*)(base + (size_t)q * DK + i * 4);
        qr[4 * i] = v.x; qr[4 * i + 1] = v.y; qr[4 * i + 2] = v.z; qr[4 * i + 3] = v.w;
    }

    __shared__ float ks[64 * DK];         // 16 KB K/V tile
    float acc[DK];
    #pragma unroll
    for (int i = 0; i < DK; i++) acc[i] = 0.0f;
    float den = 0.0f;

    for (int k0 = 0; k0 < SEQ; k0 += 64) {
        __syncthreads();
        {   // cooperative tile load: 1024 float4, 128 threads -> 8 each (coalesced)
            const float4* src = (const float4*)(base + (size_t)k0 * DK);
            float4* dst = (float4*)ks;
            #pragma unroll
            for (int i = 0; i < 8; i++) dst[threadIdx.x + i * 128] = src[threadIdx.x + i * 128];
        }
        __syncthreads();

        #pragma unroll 4
        for (int k = 0; k < 64; k++) {
            const float* kr = ks + k * DK;
            float d0 = 0.f, d1 = 0.f, d2 = 0.f, d3 = 0.f;
            #pragma unroll
            for (int i = 0; i < 16; i++) {
                float4 v = *(const float4*)(kr + 4 * i);
                d0 = fmaf(qr[4 * i],     v.x, d0);
                d1 = fmaf(qr[4 * i + 1], v.y, d1);
                d2 = fmaf(qr[4 * i + 2], v.z, d2);
                d3 = fmaf(qr[4 * i + 3], v.w, d3);
            }
            float e = exp_scaled((d0 + d1) + (d2 + d3));
            den += e;
            #pragma unroll
            for (int i = 0; i < 16; i++) {
                float4 v = *(const float4*)(kr + 4 * i);
                acc[4 * i]     = fmaf(e, v.x, acc[4 * i]);
                acc[4 * i + 1] = fmaf(e, v.y, acc[4 * i + 1]);
                acc[4 * i + 2] = fmaf(e, v.z, acc[4 * i + 2]);
                acc[4 * i + 3] = fmaf(e, v.w, acc[4 * i + 3]);
            }
        }
    }

    float inv = 1.0f / den;
    float* o = g_att + ((size_t)b * SEQ + q) * EMB + h * DK;
    #pragma unroll
    for (int i = 0; i < 16; i++) {
        float4 v;
        v.x = acc[4 * i] * inv;  v.y = acc[4 * i + 1] * inv;
        v.z = acc[4 * i + 2] * inv;  v.w = acc[4 * i + 3] * inv;
        *(float4*)(o + 4 * i) = v;
    }
}

// ---------------------------------------------------------------------------
// Stage 3: out[m,n] = sum_k att[m,k] * W[n,k] + bias[n]
// M=8192, N=1024, K=1024. 128x128x16 tile, 256 threads, 8x8 micro-tiles.
// ---------------------------------------------------------------------------
#define GM 128
#define GN 128
#define GK 16

__global__ __launch_bounds__(256) void out_gemm(const float* __restrict__ W,
                                                const float* __restrict__ bias,
                                                float* __restrict__ out) {
    __shared__ float As[GK][GM];
    __shared__ float Bs[GK][GN];
    const float* __restrict__ A = g_att;

    int bm = blockIdx.y * GM;
    int bn = blockIdx.x * GN;
    int tid = threadIdx.x;
    int tx = tid & 15, ty = tid >> 4;

    float acc[8][8];
    #pragma unroll
    for (int i = 0; i < 8; i++)
        #pragma unroll
        for (int j = 0; j < 8; j++) acc[i][j] = 0.0f;

    for (int k0 = 0; k0 < EMB; k0 += GK) {
        #pragma unroll
        for (int i = 0; i < 2; i++) {     // A tile: 128x16 = 512 float4
            int li = tid + i * 256;
            int m = li >> 2, kq = (li & 3) * 4;
            float4 v = *(const float4*)(A + (size_t)(bm + m) * EMB + k0 + kq);
            As[kq + 0][m] = v.x; As[kq + 1][m] = v.y; As[kq + 2][m] = v.z; As[kq + 3][m] = v.w;
        }
        #pragma unroll
        for (int i = 0; i < 2; i++) {     // B tile from W rows (W is [n][k])
            int li = tid + i * 256;
            int n = li >> 2, kq = (li & 3) * 4;
            float4 v = *(const float4*)(W + (size_t)(bn + n) * EMB + k0 + kq);
            Bs[kq + 0][n] = v.x; Bs[kq + 1][n] = v.y; Bs[kq + 2][n] = v.z; Bs[kq + 3][n] = v.w;
        }
        __syncthreads();

        #pragma unroll
        for (int k = 0; k < GK; k++) {
            float a[8], bb[8];
            *(float4*)(a)      = *(const float4*)&As[k][ty * 8];
            *(float4*)(a + 4)  = *(const float4*)&As[k][ty * 8 + 4];
            *(float4*)(bb)     = *(const float4*)&Bs[k][tx * 8];
            *(float4*)(bb + 4) = *(const float4*)&Bs[k][tx * 8 + 4];
            #pragma unroll
            for (int i = 0; i < 8; i++)
                #pragma unroll
                for (int j = 0; j < 8; j++)
                    acc[i][j] = fmaf(a[i], bb[j], acc[i][j]);
        }
        __syncthreads();
    }

    float bv[8];
    *(float4*)(bv)     = *(const float4*)(bias + bn + tx * 8);
    *(float4*)(bv + 4) = *(const float4*)(bias + bn + tx * 8 + 4);

    #pragma unroll
    for (int i = 0; i < 8; i++) {
        float* orow = out + (size_t)(bm + ty * 8 + i) * EMB + bn + tx * 8;
        float4 v0, v1;
        v0.x = acc[i][0] + bv[0]; v0.y = acc[i][1] + bv[1];
        v0.z = acc[i][2] + bv[2]; v0.w = acc[i][3] + bv[3];
        v1.x = acc[i][4] + bv[4]; v1.y = acc[i][5] + bv[5];
        v1.z = acc[i][6] + bv[6]; v1.w = acc[i][7] + bv[7];
        *(float4*)(orow)     = v0;
        *(float4*)(orow + 4) = v1;
    }
}

// ---------------------------------------------------------------------------
extern "C" void kernel_launch(void* const* d_in, const int* in_sizes, int n_in,
                              void* d_out, int out_size) {
    const float* x     = (const float*)d_in[0];   // [4,2048,1024]
    const float* theta = (const float*)d_in[1];   // [16,64]
    const float* w_out = (const float*)d_in[2];   // [1024,1024]
    const float* b_out = (const float*)d_in[3];   // [1024]
    float* out = (float*)d_out;                   // [4,2048,1024]

    qkv_kernel<<<(BATCH * SEQ * EMB) / 256, 256>>>(x, theta);
    attn_kernel<<<BATCH * HEADS * (SEQ / 128), 128>>>();
    dim3 ggrid(EMB / GN, (BATCH * SEQ) / GM);
    out_gemm<<<ggrid, 256>>>(w_out, b_out, out);
}

// round 7
// speedup vs baseline: 2.3982x; 2.3982x over previous
#include <cuda_runtime.h>
#include <cuda_bf16.h>
#include <cstdint>

#define BATCH 4
#define SEQ   2048
#define EMB   1024
#define HEADS 16
#define DK    64

// ---------------- device scratch (no cudaMalloc allowed) --------------------
__device__ __nv_bfloat16 g_qkv_hi[(size_t)BATCH * HEADS * SEQ * DK];
__device__ __nv_bfloat16 g_qkv_lo[(size_t)BATCH * HEADS * SEQ * DK];
__device__ __nv_bfloat16 g_att_hi[(size_t)BATCH * SEQ * EMB];
__device__ __nv_bfloat16 g_att_lo[(size_t)BATCH * SEQ * EMB];
__device__ __nv_bfloat16 g_w_hi[(size_t)EMB * EMB];
__device__ __nv_bfloat16 g_w_lo[(size_t)EMB * EMB];

// ---------------- helpers ---------------------------------------------------
__device__ __forceinline__ uint32_t smem_u32(const void* p) {
    uint32_t a;
    asm("{ .reg .u64 t; cvta.to.shared.u64 t, %1; cvt.u32.u64 %0, t; }" : "=r"(a) : "l"(p));
    return a;
}

// rows of 64 bf16 = 128B = 8 chunks of 16B; XOR swizzle for conflict-free ldmatrix
__device__ __forceinline__ uint32_t swz(uint32_t row, uint32_t chunk) {
    return row * 128u + ((chunk ^ (row & 7u)) * 16u);
}

__device__ __forceinline__ void ldsm4(uint32_t* r, uint32_t addr) {
    asm volatile("ldmatrix.sync.aligned.m8n8.x4.shared.b16 {%0,%1,%2,%3}, [%4];"
        : "=r"(r[0]), "=r"(r[1]), "=r"(r[2]), "=r"(r[3]) : "r"(addr));
}
__device__ __forceinline__ void ldsm4t(uint32_t* r, uint32_t addr) {
    asm volatile("ldmatrix.sync.aligned.m8n8.x4.trans.shared.b16 {%0,%1,%2,%3}, [%4];"
        : "=r"(r[0]), "=r"(r[1]), "=r"(r[2]), "=r"(r[3]) : "r"(addr));
}

// D = A(bf16) * B(bf16) + D(f32);  m16n8k16 row.col
__device__ __forceinline__ void mma16816(float* c, const uint32_t* a, const uint32_t* b) {
    asm volatile("mma.sync.aligned.m16n8k16.row.col.f32.bf16.bf16.f32 "
        "{%0,%1,%2,%3}, {%4,%5,%6,%7}, {%8,%9}, {%0,%1,%2,%3};"
        : "+f"(c[0]), "+f"(c[1]), "+f"(c[2]), "+f"(c[3])
        : "r"(a[0]), "r"(a[1]), "r"(a[2]), "r"(a[3]), "r"(b[0]), "r"(b[1]));
}

// exp(s * 0.125) via exp2 polynomial on the FMA pipe (no MUFU).
__device__ __forceinline__ float exp_scaled(float s) {
    const float C = 0.18033688011f;           // 0.125 * log2(e)
    float t = s * C;
    float z = t + 12582912.0f;                // 1.5 * 2^23 magic
    int   i = __float_as_int(z);
    float fi = z - 12582912.0f;
    float f = t - fi;
    float p = 1.33335581e-3f;
    p = fmaf(p, f, 9.61812910e-3f);
    p = fmaf(p, f, 5.55041087e-2f);
    p = fmaf(p, f, 2.40226512e-1f);
    p = fmaf(p, f, 6.93147182e-1f);
    p = fmaf(p, f, 1.0f);
    return __int_as_float(__float_as_int(p) + (i << 23));
}

// pack two floats into bf16x2 hi word + bf16x2 residual word (a -> low half)
__device__ __forceinline__ void split2(float a, float b, uint32_t& hi, uint32_t& lo) {
    __nv_bfloat16 ah = __float2bfloat16(a), bh = __float2bfloat16(b);
    float ar = a - __bfloat162float(ah);
    float br = b - __bfloat162float(bh);
    __nv_bfloat16 al = __float2bfloat16(ar), bl = __float2bfloat16(br);
    hi = ((uint32_t)__bfloat16_as_ushort(bh) << 16) | (uint32_t)__bfloat16_as_ushort(ah);
    lo = ((uint32_t)__bfloat16_as_ushort(bl) << 16) | (uint32_t)__bfloat16_as_ushort(al);
}

// ---------------------------------------------------------------------------
// Stage 1: qkv split = cos(x + theta) -> bf16 hi + bf16 lo residual
// ---------------------------------------------------------------------------
__global__ __launch_bounds__(256) void qkv_kernel(const float* __restrict__ x,
                                                  const float* __restrict__ theta) {
    int idx = blockIdx.x * 256 + threadIdx.x;            // over B*S*E
    int e = idx & (EMB - 1);
    int s = (idx >> 10) & (SEQ - 1);
    int b = idx >> 21;
    int h = e >> 6, d = e & (DK - 1);
    float v = cosf(x[idx] + theta[e]);
    size_t o = ((((size_t)b * HEADS + h) * SEQ) + s) * DK + d;
    __nv_bfloat16 hi = __float2bfloat16(v);
    g_qkv_hi[o] = hi;
    g_qkv_lo[o] = __float2bfloat16(v - __bfloat162float(hi));
}

__global__ __launch_bounds__(256) void wsplit_kernel(const float* __restrict__ w) {
    int idx = blockIdx.x * 256 + threadIdx.x;
    float v = w[idx];
    __nv_bfloat16 hi = __float2bfloat16(v);
    g_w_hi[idx] = hi;
    g_w_lo[idx] = __float2bfloat16(v - __bfloat162float(hi));
}

// ---------------------------------------------------------------------------
// Stage 2: attention. CTA = 128 q rows of one (b,h). 8 warps x m16.
// smem: Q hi/lo [128][64] (32KB) + K hi/lo [64][64] (16KB) = 48KB
// ---------------------------------------------------------------------------
#define AQ_H 0
#define AQ_L 16384
#define AK_H 32768
#define AK_L 40960
#define A_SMEM 49152

__global__ __launch_bounds__(256) void attn_mma() {
    extern __shared__ char smp[];
    const uint32_t sb = smem_u32(smp);
    const int tid = threadIdx.x;
    const int w = tid >> 5, lane = tid & 31;
    const int bid = blockIdx.x;                 // B*H*16
    const int qt = bid & 15, bh = bid >> 4;
    const int b = bh >> 4, h = bh & 15;
    const int q0 = qt * 128;

    const __nv_bfloat16* qh_base = g_qkv_hi + (size_t)bh * SEQ * DK;
    const __nv_bfloat16* ql_base = g_qkv_lo + (size_t)bh * SEQ * DK;

    // stage Q tile [128][64] hi/lo (swizzled)
    #pragma unroll
    for (int i = 0; i < 4; i++) {
        int idx = tid + i * 256;
        int row = idx >> 3, c = idx & 7;
        *(uint4*)(smp + AQ_H + swz(row, c)) =
            *(const uint4*)(qh_base + (size_t)(q0 + row) * DK + c * 8);
        *(uint4*)(smp + AQ_L + swz(row, c)) =
            *(const uint4*)(ql_base + (size_t)(q0 + row) * DK + c * 8);
    }
    __syncthreads();

    // Q fragments in registers: kk = k16 group (d dim), 4 regs each, hi + lo
    uint32_t qh[4][4], ql[4][4];
    #pragma unroll
    for (int kk = 0; kk < 4; kk++) {
        ldsm4(qh[kk], sb + AQ_H + swz(16 * w + (lane & 15), 2 * kk + (lane >> 4)));
        ldsm4(ql[kk], sb + AQ_L + swz(16 * w + (lane & 15), 2 * kk + (lane >> 4)));
    }

    float oacc[8][4];
    #pragma unroll
    for (int j = 0; j < 8; j++)
        #pragma unroll
        for (int r = 0; r < 4; r++) oacc[j][r] = 0.0f;
    float den0 = 0.0f, den1 = 0.0f;

    for (int t = 0; t < 32; t++) {
        const int k0 = t * 64;
        __syncthreads();
        // K/V tile [64][64] hi/lo
        #pragma unroll
        for (int i = 0; i < 2; i++) {
            int idx = tid + i * 256;
            int row = idx >> 3, c = idx & 7;
            *(uint4*)(smp + AK_H + swz(row, c)) =
                *(const uint4*)(qh_base + (size_t)(k0 + row) * DK + c * 8);
            *(uint4*)(smp + AK_L + swz(row, c)) =
                *(const uint4*)(ql_base + (size_t)(k0 + row) * DK + c * 8);
        }
        __syncthreads();

        // ---- S = Q @ K^T  (3-way hi/lo split) ----
        float sacc[8][4];
        #pragma unroll
        for (int j = 0; j < 8; j++)
            #pragma unroll
            for (int r = 0; r < 4; r++) sacc[j][r] = 0.0f;

        #pragma unroll
        for (int kk = 0; kk < 4; kk++) {
            #pragma unroll
            for (int np = 0; np < 4; np++) {
                uint32_t bh4[4], bl4[4];
                uint32_t row = 16 * np + (lane & 15), ch = 2 * kk + (lane >> 4);
                ldsm4(bh4, sb + AK_H + swz(row, ch));
                ldsm4(bl4, sb + AK_L + swz(row, ch));
                uint32_t b0h[2] = { bh4[0], bh4[2] }, b1h[2] = { bh4[1], bh4[3] };
                uint32_t b0l[2] = { bl4[0], bl4[2] }, b1l[2] = { bl4[1], bl4[3] };
                mma16816(sacc[2 * np],     qh[kk], b0h);
                mma16816(sacc[2 * np],     ql[kk], b0h);
                mma16816(sacc[2 * np],     qh[kk], b0l);
                mma16816(sacc[2 * np + 1], qh[kk], b1h);
                mma16816(sacc[2 * np + 1], ql[kk], b1h);
                mma16816(sacc[2 * np + 1], qh[kk], b1l);
            }
        }

        // ---- exp + denominator (no max pass; |S|<=8) ----
        #pragma unroll
        for (int j = 0; j < 8; j++) {
            sacc[j][0] = exp_scaled(sacc[j][0]);
            sacc[j][1] = exp_scaled(sacc[j][1]);
            sacc[j][2] = exp_scaled(sacc[j][2]);
            sacc[j][3] = exp_scaled(sacc[j][3]);
            den0 += sacc[j][0] + sacc[j][1];
            den1 += sacc[j][2] + sacc[j][3];
        }

        // ---- P: repack S accumulators directly as A fragments (hi/lo) ----
        uint32_t ph[4][4], pl[4][4];
        #pragma unroll
        for (int kk = 0; kk < 4; kk++) {
            split2(sacc[2 * kk][0],     sacc[2 * kk][1],     ph[kk][0], pl[kk][0]);
            split2(sacc[2 * kk][2],     sacc[2 * kk][3],     ph[kk][1], pl[kk][1]);
            split2(sacc[2 * kk + 1][0], sacc[2 * kk + 1][1], ph[kk][2], pl[kk][2]);
            split2(sacc[2 * kk + 1][2], sacc[2 * kk + 1][3], ph[kk][3], pl[kk][3]);
        }

        // ---- O += P @ V  (V^T via ldmatrix.trans on the same K tile) ----
        #pragma unroll
        for (int kk = 0; kk < 4; kk++) {
            #pragma unroll
            for (int ndp = 0; ndp < 4; ndp++) {
                uint32_t vh4[4], vl4[4];
                uint32_t row = 16 * kk + (lane & 7) + ((lane >> 3) & 1) * 8;
                uint32_t ch  = 2 * ndp + (lane >> 4);
                ldsm4t(vh4, sb + AK_H + swz(row, ch));
                ldsm4t(vl4, sb + AK_L + swz(row, ch));
                uint32_t v0h[2] = { vh4[0], vh4[1] }, v1h[2] = { vh4[2], vh4[3] };
                uint32_t v0l[2] = { vl4[0], vl4[1] }, v1l[2] = { vl4[2], vl4[3] };
                mma16816(oacc[2 * ndp],     ph[kk], v0h);
                mma16816(oacc[2 * ndp],     pl[kk], v0h);
                mma16816(oacc[2 * ndp],     ph[kk], v0l);
                mma16816(oacc[2 * ndp + 1], ph[kk], v1h);
                mma16816(oacc[2 * ndp + 1], pl[kk], v1h);
                mma16816(oacc[2 * ndp + 1], ph[kk], v1l);
            }
        }
    }

    // denominator: quad-reduce (lanes 4r..4r+3 hold disjoint column subsets of row r)
    den0 += __shfl_xor_sync(0xffffffffu, den0, 1);
    den0 += __shfl_xor_sync(0xffffffffu, den0, 2);
    den1 += __shfl_xor_sync(0xffffffffu, den1, 1);
    den1 += __shfl_xor_sync(0xffffffffu, den1, 2);
    float inv0 = 1.0f / den0, inv1 = 1.0f / den1;

    int r = q0 + 16 * w + (lane >> 2);
    uint32_t* oh1 = (uint32_t*)g_att_hi + ((size_t)b * SEQ + r) * 512 + h * 32 + (lane & 3);
    uint32_t* ol1 = (uint32_t*)g_att_lo + ((size_t)b * SEQ + r) * 512 + h * 32 + (lane & 3);
    uint32_t* oh2 = (uint32_t*)g_att_hi + ((size_t)b * SEQ + r + 8) * 512 + h * 32 + (lane & 3);
    uint32_t* ol2 = (uint32_t*)g_att_lo + ((size_t)b * SEQ + r + 8) * 512 + h * 32 + (lane & 3);
    #pragma unroll
    for (int nd = 0; nd < 8; nd++) {
        uint32_t hi, lo;
        split2(oacc[nd][0] * inv0, oacc[nd][1] * inv0, hi, lo);
        oh1[4 * nd] = hi; ol1[4 * nd] = lo;
        split2(oacc[nd][2] * inv1, oacc[nd][3] * inv1, hi, lo);
        oh2[4 * nd] = hi; ol2[4 * nd] = lo;
    }
}

// ---------------------------------------------------------------------------
// Stage 3: out = att @ W^T + bias. CTA tile 128x128, 8 warps (4m x 2n),
// warp tile m32 x n64, K-chunks of 64. smem 64KB.
// ---------------------------------------------------------------------------
#define OG_AH 0
#define OG_AL 16384
#define OG_BH 32768
#define OG_BL 49152
#define OG_SMEM 65536

__global__ __launch_bounds__(256) void gemm_mma(const float* __restrict__ bias,
                                                float* __restrict__ out) {
    extern __shared__ char smp[];
    const uint32_t sb = smem_u32(smp);
    const int tid = threadIdx.x;
    const int w = tid >> 5, lane = tid & 31;
    const int wy = w >> 1, wx = w & 1;
    const int bm = blockIdx.y * 128, bn = blockIdx.x * 128;

    const __nv_bfloat16* Ah = g_att_hi;
    const __nv_bfloat16* Al = g_att_lo;
    const __nv_bfloat16* Bh = g_w_hi;
    const __nv_bfloat16* Bl = g_w_lo;

    float acc[2][8][4];
    #pragma unroll
    for (int mi = 0; mi < 2; mi++)
        #pragma unroll
        for (int j = 0; j < 8; j++)
            #pragma unroll
            for (int rr = 0; rr < 4; rr++) acc[mi][j][rr] = 0.0f;

    for (int kc = 0; kc < 16; kc++) {
        const int kw = kc * 64;
        __syncthreads();
        #pragma unroll
        for (int i = 0; i < 4; i++) {
            int idx = tid + i * 256;
            int row = idx >> 3, c = idx & 7;
            *(uint4*)(smp + OG_AH + swz(row, c)) =
                *(const uint4*)(Ah + (size_t)(bm + row) * EMB + kw + c * 8);
            *(uint4*)(smp + OG_AL + swz(row, c)) =
                *(const uint4*)(Al + (size_t)(bm + row) * EMB + kw + c * 8);
            *(uint4*)(smp + OG_BH + swz(row, c)) =
                *(const uint4*)(Bh + (size_t)(bn + row) * EMB + kw + c * 8);
            *(uint4*)(smp + OG_BL + swz(row, c)) =
                *(const uint4*)(Bl + (size_t)(bn + row) * EMB + kw + c * 8);
        }
        __syncthreads();

        #pragma unroll
        for (int kk = 0; kk < 4; kk++) {
            uint32_t ah0[4], al0[4], ah1[4], al1[4];
            ldsm4(ah0, sb + OG_AH + swz(32 * wy + (lane & 15),      2 * kk + (lane >> 4)));
            ldsm4(al0, sb + OG_AL + swz(32 * wy + (lane & 15),      2 * kk + (lane >> 4)));
            ldsm4(ah1, sb + OG_AH + swz(32 * wy + 16 + (lane & 15), 2 * kk + (lane >> 4)));
            ldsm4(al1, sb + OG_AL + swz(32 * wy + 16 + (lane & 15), 2 * kk + (lane >> 4)));
            #pragma unroll
            for (int np = 0; np < 4; np++) {
                uint32_t bh4[4], bl4[4];
                uint32_t row = 64 * wx + 16 * np + (lane & 15), ch = 2 * kk + (lane >> 4);
                ldsm4(bh4, sb + OG_BH + swz(row, ch));
                ldsm4(bl4, sb + OG_BL + swz(row, ch));
                uint32_t b0h[2] = { bh4[0], bh4[2] }, b1h[2] = { bh4[1], bh4[3] };
                uint32_t b0l[2] = { bl4[0], bl4[2] }, b1l[2] = { bl4[1], bl4[3] };
                mma16816(acc[0][2 * np],     ah0, b0h);
                mma16816(acc[0][2 * np],     al0, b0h);
                mma16816(acc[0][2 * np],     ah0, b0l);
                mma16816(acc[0][2 * np + 1], ah0, b1h);
                mma16816(acc[0][2 * np + 1], al0, b1h);
                mma16816(acc[0][2 * np + 1], ah0, b1l);
                mma16816(acc[1][2 * np],     ah1, b0h);
                mma16816(acc[1][2 * np],     al1, b0h);
                mma16816(acc[1][2 * np],     ah1, b0l);
                mma16816(acc[1][2 * np + 1], ah1, b1h);
                mma16816(acc[1][2 * np + 1], al1, b1h);
                mma16816(acc[1][2 * np + 1], ah1, b1l);
            }
        }
    }

    #pragma unroll
    for (int mi = 0; mi < 2; mi++) {
        int r = bm + 32 * wy + 16 * mi + (lane >> 2);
        #pragma unroll
        for (int nt = 0; nt < 8; nt++) {
            int col = bn + 64 * wx + 8 * nt + 2 * (lane & 3);
            float bv0 = __ldg(bias + col), bv1 = __ldg(bias + col + 1);
            float2 v0, v1;
            v0.x = acc[mi][nt][0] + bv0; v0.y = acc[mi][nt][1] + bv1;
            v1.x = acc[mi][nt][2] + bv0; v1.y = acc[mi][nt][3] + bv1;
            *(float2*)(out + (size_t)r * EMB + col)       = v0;
            *(float2*)(out + (size_t)(r + 8) * EMB + col) = v1;
        }
    }
}

// ---------------------------------------------------------------------------
extern "C" void kernel_launch(void* const* d_in, const int* in_sizes, int n_in,
                              void* d_out, int out_size) {
    const float* x     = (const float*)d_in[0];   // [4,2048,1024]
    const float* theta = (const float*)d_in[1];   // [16,64]
    const float* w_out = (const float*)d_in[2];   // [1024,1024]
    const float* b_out = (const float*)d_in[3];   // [1024]
    float* out = (float*)d_out;                   // [4,2048,1024]

    cudaFuncSetAttribute(attn_mma, cudaFuncAttributeMaxDynamicSharedMemorySize, A_SMEM);
    cudaFuncSetAttribute(gemm_mma, cudaFuncAttributeMaxDynamicSharedMemorySize, OG_SMEM);

    qkv_kernel<<<(BATCH * SEQ * EMB) / 256, 256>>>(x, theta);
    wsplit_kernel<<<(EMB * EMB) / 256, 256>>>(w_out);
    attn_mma<<<BATCH * HEADS * (SEQ / 128), 256, A_SMEM>>>();
    dim3 ggrid(EMB / 128, (BATCH * SEQ) / 128);
    gemm_mma<<<ggrid, 256, OG_SMEM>>>(b_out, out);
}

// round 9
// speedup vs baseline: 2.6495x; 1.1048x over previous
#include <cuda_runtime.h>
#include <cuda_bf16.h>
#include <cstdint>

#define BATCH 4
#define SEQ   2048
#define EMB   1024
#define HEADS 16
#define DK    64

// ---------------- device scratch (no cudaMalloc allowed) --------------------
__device__ __nv_bfloat16 g_qkv_hi[(size_t)BATCH * HEADS * SEQ * DK];
__device__ __nv_bfloat16 g_qkv_lo[(size_t)BATCH * HEADS * SEQ * DK];
__device__ __nv_bfloat16 g_att_hi[(size_t)BATCH * SEQ * EMB];
__device__ __nv_bfloat16 g_att_lo[(size_t)BATCH * SEQ * EMB];
__device__ __nv_bfloat16 g_w_hi[(size_t)EMB * EMB];
__device__ __nv_bfloat16 g_w_lo[(size_t)EMB * EMB];

// ---------------- helpers ---------------------------------------------------
__device__ __forceinline__ uint32_t smem_u32(const void* p) {
    uint32_t a;
    asm("{ .reg .u64 t; cvta.to.shared.u64 t, %1; cvt.u32.u64 %0, t; }" : "=r"(a) : "l"(p));
    return a;
}

// rows of 64 bf16 = 128B = 8 chunks of 16B; XOR swizzle for conflict-free ldmatrix
__device__ __forceinline__ uint32_t swz(uint32_t row, uint32_t chunk) {
    return row * 128u + ((chunk ^ (row & 7u)) * 16u);
}

__device__ __forceinline__ void ldsm4(uint32_t* r, uint32_t addr) {
    asm volatile("ldmatrix.sync.aligned.m8n8.x4.shared.b16 {%0,%1,%2,%3}, [%4];"
        : "=r"(r[0]), "=r"(r[1]), "=r"(r[2]), "=r"(r[3]) : "r"(addr));
}
__device__ __forceinline__ void ldsm4t(uint32_t* r, uint32_t addr) {
    asm volatile("ldmatrix.sync.aligned.m8n8.x4.trans.shared.b16 {%0,%1,%2,%3}, [%4];"
        : "=r"(r[0]), "=r"(r[1]), "=r"(r[2]), "=r"(r[3]) : "r"(addr));
}

// D = A(bf16) * B(bf16) + D(f32);  m16n8k16 row.col
__device__ __forceinline__ void mma16816(float* c, const uint32_t* a, const uint32_t* b) {
    asm volatile("mma.sync.aligned.m16n8k16.row.col.f32.bf16.bf16.f32 "
        "{%0,%1,%2,%3}, {%4,%5,%6,%7}, {%8,%9}, {%0,%1,%2,%3};"
        : "+f"(c[0]), "+f"(c[1]), "+f"(c[2]), "+f"(c[3])
        : "r"(a[0]), "r"(a[1]), "r"(a[2]), "r"(a[3]), "r"(b[0]), "r"(b[1]));
}

// async copy 16B global -> shared
__device__ __forceinline__ void cpa16(uint32_t saddr, const void* gaddr) {
    asm volatile("cp.async.cg.shared.global [%0], [%1], 16;" :: "r"(saddr), "l"(gaddr));
}
#define CP_COMMIT() asm volatile("cp.async.commit_group;" ::: "memory")
#define CP_WAIT0()  asm volatile("cp.async.wait_group 0;" ::: "memory")

// exp(s * 0.125) via exp2 polynomial on the FMA pipe (no MUFU).
__device__ __forceinline__ float exp_scaled(float s) {
    const float C = 0.18033688011f;           // 0.125 * log2(e)
    float t = s * C;
    float z = t + 12582912.0f;                // 1.5 * 2^23 magic
    int   i = __float_as_int(z);
    float fi = z - 12582912.0f;
    float f = t - fi;
    float p = 1.33335581e-3f;
    p = fmaf(p, f, 9.61812910e-3f);
    p = fmaf(p, f, 5.55041087e-2f);
    p = fmaf(p, f, 2.40226512e-1f);
    p = fmaf(p, f, 6.93147182e-1f);
    p = fmaf(p, f, 1.0f);
    return __int_as_float(__float_as_int(p) + (i << 23));
}

// pack two floats into bf16x2 hi word + bf16x2 residual word (a -> low half)
__device__ __forceinline__ void split2(float a, float b, uint32_t& hi, uint32_t& lo) {
    __nv_bfloat16 ah = __float2bfloat16(a), bh = __float2bfloat16(b);
    float ar = a - __bfloat162float(ah);
    float br = b - __bfloat162float(bh);
    __nv_bfloat16 al = __float2bfloat16(ar), bl = __float2bfloat16(br);
    hi = ((uint32_t)__bfloat16_as_ushort(bh) << 16) | (uint32_t)__bfloat16_as_ushort(ah);
    lo = ((uint32_t)__bfloat16_as_ushort(bl) << 16) | (uint32_t)__bfloat16_as_ushort(al);
}

// ---------------------------------------------------------------------------
// Stage 1: qkv split = cos(x + theta) -> bf16 hi + bf16 lo residual
// ---------------------------------------------------------------------------
__global__ __launch_bounds__(256) void qkv_kernel(const float* __restrict__ x,
                                                  const float* __restrict__ theta) {
    int idx = blockIdx.x * 256 + threadIdx.x;            // over B*S*E
    int e = idx & (EMB - 1);
    int s = (idx >> 10) & (SEQ - 1);
    int b = idx >> 21;
    int h = e >> 6, d = e & (DK - 1);
    float v = cosf(x[idx] + theta[e]);
    size_t o = ((((size_t)b * HEADS + h) * SEQ) + s) * DK + d;
    __nv_bfloat16 hi = __float2bfloat16(v);
    g_qkv_hi[o] = hi;
    g_qkv_lo[o] = __float2bfloat16(v - __bfloat162float(hi));
}

__global__ __launch_bounds__(256) void wsplit_kernel(const float* __restrict__ w) {
    int idx = blockIdx.x * 256 + threadIdx.x;
    float v = w[idx];
    __nv_bfloat16 hi = __float2bfloat16(v);
    g_w_hi[idx] = hi;
    g_w_lo[idx] = __float2bfloat16(v - __bfloat162float(hi));
}

// ---------------------------------------------------------------------------
// Stage 2: attention. CTA = 128 q rows of one (b,h). 8 warps x m16.
// smem: Q hi/lo [128][64] (32KB) + 2-stage K ring (2 x 16KB) = 64KB
// cp.async double-buffered: load tile t+1 while computing tile t.
// ---------------------------------------------------------------------------
#define AQ_H 0
#define AQ_L 16384
#define AK0  32768      // stage 0: hi at +0, lo at +8192
#define AK1  49152      // stage 1
#define A_SMEM 65536

__global__ __launch_bounds__(256) void attn_mma() {
    extern __shared__ char smp[];
    const uint32_t sb = smem_u32(smp);
    const int tid = threadIdx.x;
    const int w = tid >> 5, lane = tid & 31;
    const int bid = blockIdx.x;                 // B*H*16
    const int qt = bid & 15, bh = bid >> 4;
    const int b = bh >> 4, h = bh & 15;
    const int q0 = qt * 128;

    const __nv_bfloat16* qh_base = g_qkv_hi + (size_t)bh * SEQ * DK;
    const __nv_bfloat16* ql_base = g_qkv_lo + (size_t)bh * SEQ * DK;

    // per-thread K-tile load slots (2 x 16B hi + 2 x 16B lo)
    const int lrow0 = tid >> 3,        lc0 = tid & 7;
    const int lrow1 = (tid + 256) >> 3, lc1 = tid & 7;
    const uint32_t sw0 = swz(lrow0, lc0), sw1 = swz(lrow1, lc1);

    // prologue: issue K tile 0 into stage 0
    {
        cpa16(sb + AK0 + sw0,        qh_base + (size_t)lrow0 * DK + lc0 * 8);
        cpa16(sb + AK0 + sw1,        qh_base + (size_t)lrow1 * DK + lc1 * 8);
        cpa16(sb + AK0 + 8192 + sw0, ql_base + (size_t)lrow0 * DK + lc0 * 8);
        cpa16(sb + AK0 + 8192 + sw1, ql_base + (size_t)lrow1 * DK + lc1 * 8);
        CP_COMMIT();
    }

    // stage Q tile [128][64] hi/lo (swizzled), overlaps with tile-0 cp.async
    #pragma unroll
    for (int i = 0; i < 4; i++) {
        int idx = tid + i * 256;
        int row = idx >> 3, c = idx & 7;
        *(uint4*)(smp + AQ_H + swz(row, c)) =
            *(const uint4*)(qh_base + (size_t)(q0 + row) * DK + c * 8);
        *(uint4*)(smp + AQ_L + swz(row, c)) =
            *(const uint4*)(ql_base + (size_t)(q0 + row) * DK + c * 8);
    }
    __syncthreads();

    // Q fragments in registers: kk = k16 group (d dim), 4 regs each, hi + lo
    uint32_t qh[4][4], ql[4][4];
    #pragma unroll
    for (int kk = 0; kk < 4; kk++) {
        ldsm4(qh[kk], sb + AQ_H + swz(16 * w + (lane & 15), 2 * kk + (lane >> 4)));
        ldsm4(ql[kk], sb + AQ_L + swz(16 * w + (lane & 15), 2 * kk + (lane >> 4)));
    }

    float oacc[8][4];
    #pragma unroll
    for (int j = 0; j < 8; j++)
        #pragma unroll
        for (int r = 0; r < 4; r++) oacc[j][r] = 0.0f;
    float den0 = 0.0f, den1 = 0.0f;

    for (int t = 0; t < 32; t++) {
        const uint32_t kb  = (t & 1) ? AK1 : AK0;
        const uint32_t kbn = (t & 1) ? AK0 : AK1;

        CP_WAIT0();            // tile t resident
        __syncthreads();       // all warps done with compute t-1 (stage kbn)

        if (t + 1 < 32) {      // prefetch tile t+1 into the other stage
            const __nv_bfloat16* gh = qh_base + (size_t)(t + 1) * 64 * DK;
            const __nv_bfloat16* gl = ql_base + (size_t)(t + 1) * 64 * DK;
            cpa16(sb + kbn + sw0,        gh + (size_t)lrow0 * DK + lc0 * 8);
            cpa16(sb + kbn + sw1,        gh + (size_t)lrow1 * DK + lc1 * 8);
            cpa16(sb + kbn + 8192 + sw0, gl + (size_t)lrow0 * DK + lc0 * 8);
            cpa16(sb + kbn + 8192 + sw1, gl + (size_t)lrow1 * DK + lc1 * 8);
            CP_COMMIT();
        }

        const uint32_t kH = sb + kb, kL = sb + kb + 8192;

        // ---- S = Q @ K^T  (3-way hi/lo split) ----
        float sacc[8][4];
        #pragma unroll
        for (int j = 0; j < 8; j++)
            #pragma unroll
            for (int r = 0; r < 4; r++) sacc[j][r] = 0.0f;

        #pragma unroll
        for (int kk = 0; kk < 4; kk++) {
            #pragma unroll
            for (int np = 0; np < 4; np++) {
                uint32_t bh4[4], bl4[4];
                uint32_t row = 16 * np + (lane & 15), ch = 2 * kk + (lane >> 4);
                ldsm4(bh4, kH + swz(row, ch));
                ldsm4(bl4, kL + swz(row, ch));
                uint32_t b0h[2] = { bh4[0], bh4[2] }, b1h[2] = { bh4[1], bh4[3] };
                uint32_t b0l[2] = { bl4[0], bl4[2] }, b1l[2] = { bl4[1], bl4[3] };
                mma16816(sacc[2 * np],     qh[kk], b0h);
                mma16816(sacc[2 * np],     ql[kk], b0h);
                mma16816(sacc[2 * np],     qh[kk], b0l);
                mma16816(sacc[2 * np + 1], qh[kk], b1h);
                mma16816(sacc[2 * np + 1], ql[kk], b1h);
                mma16816(sacc[2 * np + 1], qh[kk], b1l);
            }
        }

        // ---- exp + denominator (no max pass; |S|<=8) ----
        #pragma unroll
        for (int j = 0; j < 8; j++) {
            sacc[j][0] = exp_scaled(sacc[j][0]);
            sacc[j][1] = exp_scaled(sacc[j][1]);
            sacc[j][2] = exp_scaled(sacc[j][2]);
            sacc[j][3] = exp_scaled(sacc[j][3]);
            den0 += sacc[j][0] + sacc[j][1];
            den1 += sacc[j][2] + sacc[j][3];
        }

        // ---- P: repack S accumulators directly as A fragments (hi/lo) ----
        uint32_t ph[4][4], pl[4][4];
        #pragma unroll
        for (int kk = 0; kk < 4; kk++) {
            split2(sacc[2 * kk][0],     sacc[2 * kk][1],     ph[kk][0], pl[kk][0]);
            split2(sacc[2 * kk][2],     sacc[2 * kk][3],     ph[kk][1], pl[kk][1]);
            split2(sacc[2 * kk + 1][0], sacc[2 * kk + 1][1], ph[kk][2], pl[kk][2]);
            split2(sacc[2 * kk + 1][2], sacc[2 * kk + 1][3], ph[kk][3], pl[kk][3]);
        }

        // ---- O += P @ V  (V^T via ldmatrix.trans on the same K tile) ----
        #pragma unroll
        for (int kk = 0; kk < 4; kk++) {
            #pragma unroll
            for (int ndp = 0; ndp < 4; ndp++) {
                uint32_t vh4[4], vl4[4];
                uint32_t row = 16 * kk + (lane & 7) + ((lane >> 3) & 1) * 8;
                uint32_t ch  = 2 * ndp + (lane >> 4);
                ldsm4t(vh4, kH + swz(row, ch));
                ldsm4t(vl4, kL + swz(row, ch));
                uint32_t v0h[2] = { vh4[0], vh4[1] }, v1h[2] = { vh4[2], vh4[3] };
                uint32_t v0l[2] = { vl4[0], vl4[1] }, v1l[2] = { vl4[2], vl4[3] };
                mma16816(oacc[2 * ndp],     ph[kk], v0h);
                mma16816(oacc[2 * ndp],     pl[kk], v0h);
                mma16816(oacc[2 * ndp],     ph[kk], v0l);
                mma16816(oacc[2 * ndp + 1], ph[kk], v1h);
                mma16816(oacc[2 * ndp + 1], pl[kk], v1h);
                mma16816(oacc[2 * ndp + 1], ph[kk], v1l);
            }
        }
    }

    // denominator: quad-reduce (lanes 4r..4r+3 hold disjoint column subsets of row r)
    den0 += __shfl_xor_sync(0xffffffffu, den0, 1);
    den0 += __shfl_xor_sync(0xffffffffu, den0, 2);
    den1 += __shfl_xor_sync(0xffffffffu, den1, 1);
    den1 += __shfl_xor_sync(0xffffffffu, den1, 2);
    float inv0 = 1.0f / den0, inv1 = 1.0f / den1;

    int r = q0 + 16 * w + (lane >> 2);
    uint32_t* oh1 = (uint32_t*)g_att_hi + ((size_t)b * SEQ + r) * 512 + h * 32 + (lane & 3);
    uint32_t* ol1 = (uint32_t*)g_att_lo + ((size_t)b * SEQ + r) * 512 + h * 32 + (lane & 3);
    uint32_t* oh2 = (uint32_t*)g_att_hi + ((size_t)b * SEQ + r + 8) * 512 + h * 32 + (lane & 3);
    uint32_t* ol2 = (uint32_t*)g_att_lo + ((size_t)b * SEQ + r + 8) * 512 + h * 32 + (lane & 3);
    #pragma unroll
    for (int nd = 0; nd < 8; nd++) {
        uint32_t hi, lo;
        split2(oacc[nd][0] * inv0, oacc[nd][1] * inv0, hi, lo);
        oh1[4 * nd] = hi; ol1[4 * nd] = lo;
        split2(oacc[nd][2] * inv1, oacc[nd][3] * inv1, hi, lo);
        oh2[4 * nd] = hi; ol2[4 * nd] = lo;
    }
}

// ---------------------------------------------------------------------------
// Stage 3: out = att @ W^T + bias. CTA tile 128x128, 8 warps (4m x 2n),
// warp tile m32 x n64, K-chunks of 64. 2-stage cp.async pipeline, 128KB smem.
// ---------------------------------------------------------------------------
#define OG_STAGE 65536       // per-stage: AH +0, AL +16384, BH +32768, BL +49152
#define OG_SMEM  131072

__global__ __launch_bounds__(256) void gemm_mma(const float* __restrict__ bias,
                                                float* __restrict__ out) {
    extern __shared__ char smp[];
    const uint32_t sb = smem_u32(smp);
    const int tid = threadIdx.x;
    const int w = tid >> 5, lane = tid & 31;
    const int wy = w >> 1, wx = w & 1;
    const int bm = blockIdx.y * 128, bn = blockIdx.x * 128;

    const __nv_bfloat16* Ah = g_att_hi;
    const __nv_bfloat16* Al = g_att_lo;
    const __nv_bfloat16* Bh = g_w_hi;
    const __nv_bfloat16* Bl = g_w_lo;

    float acc[2][8][4];
    #pragma unroll
    for (int mi = 0; mi < 2; mi++)
        #pragma unroll
        for (int j = 0; j < 8; j++)
            #pragma unroll
            for (int rr = 0; rr < 4; rr++) acc[mi][j][rr] = 0.0f;

    // chunk loader: 64KB per k-chunk via cp.async into stage base ss
    auto issue_chunk = [&](int kc, uint32_t ss) {
        const int kw = kc * 64;
        #pragma unroll
        for (int i = 0; i < 4; i++) {
            int idx = tid + i * 256;
            int row = idx >> 3, c = idx & 7;
            uint32_t sw = swz(row, c);
            cpa16(ss + sw,         Ah + (size_t)(bm + row) * EMB + kw + c * 8);
            cpa16(ss + 16384 + sw, Al + (size_t)(bm + row) * EMB + kw + c * 8);
            cpa16(ss + 32768 + sw, Bh + (size_t)(bn + row) * EMB + kw + c * 8);
            cpa16(ss + 49152 + sw, Bl + (size_t)(bn + row) * EMB + kw + c * 8);
        }
        CP_COMMIT();
    };

    issue_chunk(0, sb);

    for (int kc = 0; kc < 16; kc++) {
        const uint32_t ss  = sb + (kc & 1) * OG_STAGE;
        const uint32_t ssn = sb + ((kc + 1) & 1) * OG_STAGE;

        CP_WAIT0();
        __syncthreads();
        if (kc + 1 < 16) issue_chunk(kc + 1, ssn);

        #pragma unroll
        for (int kk = 0; kk < 4; kk++) {
            uint32_t ah0[4], al0[4], ah1[4], al1[4];
            ldsm4(ah0, ss + swz(32 * wy + (lane & 15),      2 * kk + (lane >> 4)));
            ldsm4(al0, ss + 16384 + swz(32 * wy + (lane & 15),      2 * kk + (lane >> 4)));
            ldsm4(ah1, ss + swz(32 * wy + 16 + (lane & 15), 2 * kk + (lane >> 4)));
            ldsm4(al1, ss + 16384 + swz(32 * wy + 16 + (lane & 15), 2 * kk + (lane >> 4)));
            #pragma unroll
            for (int np = 0; np < 4; np++) {
                uint32_t bh4[4], bl4[4];
                uint32_t row = 64 * wx + 16 * np + (lane & 15), ch = 2 * kk + (lane >> 4);
                ldsm4(bh4, ss + 32768 + swz(row, ch));
                ldsm4(bl4, ss + 49152 + swz(row, ch));
                uint32_t b0h[2] = { bh4[0], bh4[2] }, b1h[2] = { bh4[1], bh4[3] };
                uint32_t b0l[2] = { bl4[0], bl4[2] }, b1l[2] = { bl4[1], bl4[3] };
                mma16816(acc[0][2 * np],     ah0, b0h);
                mma16816(acc[0][2 * np],     al0, b0h);
                mma16816(acc[0][2 * np],     ah0, b0l);
                mma16816(acc[0][2 * np + 1], ah0, b1h);
                mma16816(acc[0][2 * np + 1], al0, b1h);
                mma16816(acc[0][2 * np + 1], ah0, b1l);
                mma16816(acc[1][2 * np],     ah1, b0h);
                mma16816(acc[1][2 * np],     al1, b0h);
                mma16816(acc[1][2 * np],     ah1, b0l);
                mma16816(acc[1][2 * np + 1], ah1, b1h);
                mma16816(acc[1][2 * np + 1], al1, b1h);
                mma16816(acc[1][2 * np + 1], ah1, b1l);
            }
        }
    }

    #pragma unroll
    for (int mi = 0; mi < 2; mi++) {
        int r = bm + 32 * wy + 16 * mi + (lane >> 2);
        #pragma unroll
        for (int nt = 0; nt < 8; nt++) {
            int col = bn + 64 * wx + 8 * nt + 2 * (lane & 3);
            float bv0 = __ldg(bias + col), bv1 = __ldg(bias + col + 1);
            float2 v0, v1;
            v0.x = acc[mi][nt][0] + bv0; v0.y = acc[mi][nt][1] + bv1;
            v1.x = acc[mi][nt][2] + bv0; v1.y = acc[mi][nt][3] + bv1;
            *(float2*)(out + (size_t)r * EMB + col)       = v0;
            *(float2*)(out + (size_t)(r + 8) * EMB + col) = v1;
        }
    }
}

// ---------------------------------------------------------------------------
extern "C" void kernel_launch(void* const* d_in, const int* in_sizes, int n_in,
                              void* d_out, int out_size) {
    const float* x     = (const float*)d_in[0];   // [4,2048,1024]
    const float* theta = (const float*)d_in[1];   // [16,64]
    const float* w_out = (const float*)d_in[2];   // [1024,1024]
    const float* b_out = (const float*)d_in[3];   // [1024]
    float* out = (float*)d_out;                   // [4,2048,1024]

    cudaFuncSetAttribute(attn_mma, cudaFuncAttributeMaxDynamicSharedMemorySize, A_SMEM);
    cudaFuncSetAttribute(gemm_mma, cudaFuncAttributeMaxDynamicSharedMemorySize, OG_SMEM);

    qkv_kernel<<<(BATCH * SEQ * EMB) / 256, 256>>>(x, theta);
    wsplit_kernel<<<(EMB * EMB) / 256, 256>>>(w_out);
    attn_mma<<<BATCH * HEADS * (SEQ / 128), 256, A_SMEM>>>();
    dim3 ggrid(EMB / 128, (BATCH * SEQ) / 128);
    gemm_mma<<<ggrid, 256, OG_SMEM>>>(b_out, out);
}

// round 11
// speedup vs baseline: 3.0510x; 1.1516x over previous
#include <cuda_runtime.h>
#include <cuda_bf16.h>
#include <cstdint>

#define BATCH 4
#define SEQ   2048
#define EMB   1024
#define HEADS 16
#define DK    64

// ---------------- device scratch (no cudaMalloc allowed) --------------------
__device__ __nv_bfloat16 g_qkv_hi[(size_t)BATCH * HEADS * SEQ * DK];
__device__ __nv_bfloat16 g_qkv_lo[(size_t)BATCH * HEADS * SEQ * DK];
__device__ __nv_bfloat16 g_att_hi[(size_t)BATCH * SEQ * EMB];
__device__ __nv_bfloat16 g_att_lo[(size_t)BATCH * SEQ * EMB];
__device__ __nv_bfloat16 g_w_hi[(size_t)EMB * EMB];
__device__ __nv_bfloat16 g_w_lo[(size_t)EMB * EMB];

// ---------------- helpers ---------------------------------------------------
__device__ __forceinline__ uint32_t smem_u32(const void* p) {
    uint32_t a;
    asm("{ .reg .u64 t; cvta.to.shared.u64 t, %1; cvt.u32.u64 %0, t; }" : "=r"(a) : "l"(p));
    return a;
}

// 128B rows (64 bf16): 8 chunks of 16B, XOR swizzle -> conflict-free ldmatrix
__device__ __forceinline__ uint32_t swz(uint32_t row, uint32_t chunk) {
    return row * 128u + ((chunk ^ (row & 7u)) * 16u);
}
// 64B rows (32 bf16): 4 chunks of 16B. chunk ^ ((row>>1)&3) puts the 8 rows of
// an ldmatrix read into 8 distinct 16B slots (2 half-lines x 4 chunks).
__device__ __forceinline__ uint32_t swz32(uint32_t row, uint32_t chunk) {
    return row * 64u + ((chunk ^ ((row >> 1) & 3u)) * 16u);
}

__device__ __forceinline__ void ldsm4(uint32_t* r, uint32_t addr) {
    asm volatile("ldmatrix.sync.aligned.m8n8.x4.shared.b16 {%0,%1,%2,%3}, [%4];"
        : "=r"(r[0]), "=r"(r[1]), "=r"(r[2]), "=r"(r[3]) : "r"(addr));
}
__device__ __forceinline__ void ldsm4t(uint32_t* r, uint32_t addr) {
    asm volatile("ldmatrix.sync.aligned.m8n8.x4.trans.shared.b16 {%0,%1,%2,%3}, [%4];"
        : "=r"(r[0]), "=r"(r[1]), "=r"(r[2]), "=r"(r[3]) : "r"(addr));
}

// D = A(bf16) * B(bf16) + D(f32);  m16n8k16 row.col
__device__ __forceinline__ void mma16816(float* c, const uint32_t* a, const uint32_t* b) {
    asm volatile("mma.sync.aligned.m16n8k16.row.col.f32.bf16.bf16.f32 "
        "{%0,%1,%2,%3}, {%4,%5,%6,%7}, {%8,%9}, {%0,%1,%2,%3};"
        : "+f"(c[0]), "+f"(c[1]), "+f"(c[2]), "+f"(c[3])
        : "r"(a[0]), "r"(a[1]), "r"(a[2]), "r"(a[3]), "r"(b[0]), "r"(b[1]));
}

// async copy 16B global -> shared
__device__ __forceinline__ void cpa16(uint32_t saddr, const void* gaddr) {
    asm volatile("cp.async.cg.shared.global [%0], [%1], 16;" :: "r"(saddr), "l"(gaddr));
}
#define CP_COMMIT() asm volatile("cp.async.commit_group;" ::: "memory")
#define CP_WAIT0()  asm volatile("cp.async.wait_group 0;" ::: "memory")

// exp(s * 0.125) via exp2 polynomial on the FMA pipe (no MUFU).
__device__ __forceinline__ float exp_scaled(float s) {
    const float C = 0.18033688011f;           // 0.125 * log2(e)
    float t = s * C;
    float z = t + 12582912.0f;                // 1.5 * 2^23 magic
    int   i = __float_as_int(z);
    float fi = z - 12582912.0f;
    float f = t - fi;
    float p = 1.33335581e-3f;
    p = fmaf(p, f, 9.61812910e-3f);
    p = fmaf(p, f, 5.55041087e-2f);
    p = fmaf(p, f, 2.40226512e-1f);
    p = fmaf(p, f, 6.93147182e-1f);
    p = fmaf(p, f, 1.0f);
    return __int_as_float(__float_as_int(p) + (i << 23));
}

// pack two floats into bf16x2 hi word + bf16x2 residual word (a -> low half)
__device__ __forceinline__ void split2(float a, float b, uint32_t& hi, uint32_t& lo) {
    __nv_bfloat16 ah = __float2bfloat16(a), bh = __float2bfloat16(b);
    float ar = a - __bfloat162float(ah);
    float br = b - __bfloat162float(bh);
    __nv_bfloat16 al = __float2bfloat16(ar), bl = __float2bfloat16(br);
    hi = ((uint32_t)__bfloat16_as_ushort(bh) << 16) | (uint32_t)__bfloat16_as_ushort(ah);
    lo = ((uint32_t)__bfloat16_as_ushort(bl) << 16) | (uint32_t)__bfloat16_as_ushort(al);
}

// ---------------------------------------------------------------------------
// Stage 1: qkv split = cos(x + theta) -> bf16 hi + bf16 lo residual
// ---------------------------------------------------------------------------
__global__ __launch_bounds__(256) void qkv_kernel(const float* __restrict__ x,
                                                  const float* __restrict__ theta) {
    int idx = blockIdx.x * 256 + threadIdx.x;            // over B*S*E
    int e = idx & (EMB - 1);
    int s = (idx >> 10) & (SEQ - 1);
    int b = idx >> 21;
    int h = e >> 6, d = e & (DK - 1);
    float v = cosf(x[idx] + theta[e]);
    size_t o = ((((size_t)b * HEADS + h) * SEQ) + s) * DK + d;
    __nv_bfloat16 hi = __float2bfloat16(v);
    g_qkv_hi[o] = hi;
    g_qkv_lo[o] = __float2bfloat16(v - __bfloat162float(hi));
}

__global__ __launch_bounds__(256) void wsplit_kernel(const float* __restrict__ w) {
    int idx = blockIdx.x * 256 + threadIdx.x;
    float v = w[idx];
    __nv_bfloat16 hi = __float2bfloat16(v);
    g_w_hi[idx] = hi;
    g_w_lo[idx] = __float2bfloat16(v - __bfloat162float(hi));
}

// ---------------------------------------------------------------------------
// Stage 2: attention. CTA = 128 q rows of one (b,h). 8 warps x m16.
// smem: Q hi/lo [128][64] (32KB) + 2-stage K ring (2 x 16KB) = 64KB
// __launch_bounds__(256,2) -> 2 CTAs/SM, 4 warps/SMSP.
// ---------------------------------------------------------------------------
#define AQ_H 0
#define AQ_L 16384
#define AK0  32768      // stage 0: hi at +0, lo at +8192
#define AK1  49152      // stage 1
#define A_SMEM 65536

__global__ __launch_bounds__(256, 2) void attn_mma() {
    extern __shared__ char smp[];
    const uint32_t sb = smem_u32(smp);
    const int tid = threadIdx.x;
    const int w = tid >> 5, lane = tid & 31;
    const int bid = blockIdx.x;                 // B*H*16
    const int qt = bid & 15, bh = bid >> 4;
    const int b = bh >> 4, h = bh & 15;
    const int q0 = qt * 128;

    const __nv_bfloat16* qh_base = g_qkv_hi + (size_t)bh * SEQ * DK;
    const __nv_bfloat16* ql_base = g_qkv_lo + (size_t)bh * SEQ * DK;

    // per-thread K-tile load slots (2 x 16B hi + 2 x 16B lo)
    const int lrow0 = tid >> 3,        lc0 = tid & 7;
    const int lrow1 = (tid + 256) >> 3, lc1 = tid & 7;
    const uint32_t sw0 = swz(lrow0, lc0), sw1 = swz(lrow1, lc1);

    // prologue: issue K tile 0 into stage 0
    {
        cpa16(sb + AK0 + sw0,        qh_base + (size_t)lrow0 * DK + lc0 * 8);
        cpa16(sb + AK0 + sw1,        qh_base + (size_t)lrow1 * DK + lc1 * 8);
        cpa16(sb + AK0 + 8192 + sw0, ql_base + (size_t)lrow0 * DK + lc0 * 8);
        cpa16(sb + AK0 + 8192 + sw1, ql_base + (size_t)lrow1 * DK + lc1 * 8);
        CP_COMMIT();
    }

    // stage Q tile [128][64] hi/lo (swizzled), overlaps with tile-0 cp.async
    #pragma unroll
    for (int i = 0; i < 4; i++) {
        int idx = tid + i * 256;
        int row = idx >> 3, c = idx & 7;
        *(uint4*)(smp + AQ_H + swz(row, c)) =
            *(const uint4*)(qh_base + (size_t)(q0 + row) * DK + c * 8);
        *(uint4*)(smp + AQ_L + swz(row, c)) =
            *(const uint4*)(ql_base + (size_t)(q0 + row) * DK + c * 8);
    }
    __syncthreads();

    // Q fragments in registers: kk = k16 group (d dim), 4 regs each, hi + lo
    uint32_t qh[4][4], ql[4][4];
    #pragma unroll
    for (int kk = 0; kk < 4; kk++) {
        ldsm4(qh[kk], sb + AQ_H + swz(16 * w + (lane & 15), 2 * kk + (lane >> 4)));
        ldsm4(ql[kk], sb + AQ_L + swz(16 * w + (lane & 15), 2 * kk + (lane >> 4)));
    }

    float oacc[8][4];
    #pragma unroll
    for (int j = 0; j < 8; j++)
        #pragma unroll
        for (int r = 0; r < 4; r++) oacc[j][r] = 0.0f;
    float den0 = 0.0f, den1 = 0.0f;

    for (int t = 0; t < 32; t++) {
        const uint32_t kb  = (t & 1) ? AK1 : AK0;
        const uint32_t kbn = (t & 1) ? AK0 : AK1;

        CP_WAIT0();            // tile t resident
        __syncthreads();       // all warps done with compute t-1 (stage kbn)

        if (t + 1 < 32) {      // prefetch tile t+1 into the other stage
            const __nv_bfloat16* gh = qh_base + (size_t)(t + 1) * 64 * DK;
            const __nv_bfloat16* gl = ql_base + (size_t)(t + 1) * 64 * DK;
            cpa16(sb + kbn + sw0,        gh + (size_t)lrow0 * DK + lc0 * 8);
            cpa16(sb + kbn + sw1,        gh + (size_t)lrow1 * DK + lc1 * 8);
            cpa16(sb + kbn + 8192 + sw0, gl + (size_t)lrow0 * DK + lc0 * 8);
            cpa16(sb + kbn + 8192 + sw1, gl + (size_t)lrow1 * DK + lc1 * 8);
            CP_COMMIT();
        }

        const uint32_t kH = sb + kb, kL = sb + kb + 8192;

        // ---- S = Q @ K^T  (3-way hi/lo split), round-major MMA order ----
        float sacc[8][4];
        #pragma unroll
        for (int j = 0; j < 8; j++)
            #pragma unroll
            for (int r = 0; r < 4; r++) sacc[j][r] = 0.0f;

        #pragma unroll
        for (int kk = 0; kk < 4; kk++) {
            #pragma unroll
            for (int np = 0; np < 4; np++) {
                uint32_t bh4[4], bl4[4];
                uint32_t row = 16 * np + (lane & 15), ch = 2 * kk + (lane >> 4);
                ldsm4(bh4, kH + swz(row, ch));
                ldsm4(bl4, kL + swz(row, ch));
                uint32_t b0h[2] = { bh4[0], bh4[2] }, b1h[2] = { bh4[1], bh4[3] };
                uint32_t b0l[2] = { bl4[0], bl4[2] }, b1l[2] = { bl4[1], bl4[3] };
                mma16816(sacc[2 * np],     qh[kk], b0h);
                mma16816(sacc[2 * np + 1], qh[kk], b1h);
                mma16816(sacc[2 * np],     ql[kk], b0h);
                mma16816(sacc[2 * np + 1], ql[kk], b1h);
                mma16816(sacc[2 * np],     qh[kk], b0l);
                mma16816(sacc[2 * np + 1], qh[kk], b1l);
            }
        }

        // ---- exp + denominator (no max pass; |S|<=8) ----
        #pragma unroll
        for (int j = 0; j < 8; j++) {
            sacc[j][0] = exp_scaled(sacc[j][0]);
            sacc[j][1] = exp_scaled(sacc[j][1]);
            sacc[j][2] = exp_scaled(sacc[j][2]);
            sacc[j][3] = exp_scaled(sacc[j][3]);
            den0 += sacc[j][0] + sacc[j][1];
            den1 += sacc[j][2] + sacc[j][3];
        }

        // ---- P: repack S accumulators directly as A fragments (hi/lo) ----
        uint32_t ph[4][4], pl[4][4];
        #pragma unroll
        for (int kk = 0; kk < 4; kk++) {
            split2(sacc[2 * kk][0],     sacc[2 * kk][1],     ph[kk][0], pl[kk][0]);
            split2(sacc[2 * kk][2],     sacc[2 * kk][3],     ph[kk][1], pl[kk][1]);
            split2(sacc[2 * kk + 1][0], sacc[2 * kk + 1][1], ph[kk][2], pl[kk][2]);
            split2(sacc[2 * kk + 1][2], sacc[2 * kk + 1][3], ph[kk][3], pl[kk][3]);
        }

        // ---- O += P @ V  (V^T via ldmatrix.trans on the same K tile) ----
        #pragma unroll
        for (int kk = 0; kk < 4; kk++) {
            #pragma unroll
            for (int ndp = 0; ndp < 4; ndp++) {
                uint32_t vh4[4], vl4[4];
                uint32_t row = 16 * kk + (lane & 7) + ((lane >> 3) & 1) * 8;
                uint32_t ch  = 2 * ndp + (lane >> 4);
                ldsm4t(vh4, kH + swz(row, ch));
                ldsm4t(vl4, kL + swz(row, ch));
                uint32_t v0h[2] = { vh4[0], vh4[1] }, v1h[2] = { vh4[2], vh4[3] };
                uint32_t v0l[2] = { vl4[0], vl4[1] }, v1l[2] = { vl4[2], vl4[3] };
                mma16816(oacc[2 * ndp],     ph[kk], v0h);
                mma16816(oacc[2 * ndp + 1], ph[kk], v1h);
                mma16816(oacc[2 * ndp],     pl[kk], v0h);
                mma16816(oacc[2 * ndp + 1], pl[kk], v1h);
                mma16816(oacc[2 * ndp],     ph[kk], v0l);
                mma16816(oacc[2 * ndp + 1], ph[kk], v1l);
            }
        }
    }

    // denominator: quad-reduce (lanes 4r..4r+3 hold disjoint column subsets of row r)
    den0 += __shfl_xor_sync(0xffffffffu, den0, 1);
    den0 += __shfl_xor_sync(0xffffffffu, den0, 2);
    den1 += __shfl_xor_sync(0xffffffffu, den1, 1);
    den1 += __shfl_xor_sync(0xffffffffu, den1, 2);
    float inv0 = 1.0f / den0, inv1 = 1.0f / den1;

    int r = q0 + 16 * w + (lane >> 2);
    uint32_t* oh1 = (uint32_t*)g_att_hi + ((size_t)b * SEQ + r) * 512 + h * 32 + (lane & 3);
    uint32_t* ol1 = (uint32_t*)g_att_lo + ((size_t)b * SEQ + r) * 512 + h * 32 + (lane & 3);
    uint32_t* oh2 = (uint32_t*)g_att_hi + ((size_t)b * SEQ + r + 8) * 512 + h * 32 + (lane & 3);
    uint32_t* ol2 = (uint32_t*)g_att_lo + ((size_t)b * SEQ + r + 8) * 512 + h * 32 + (lane & 3);
    #pragma unroll
    for (int nd = 0; nd < 8; nd++) {
        uint32_t hi, lo;
        split2(oacc[nd][0] * inv0, oacc[nd][1] * inv0, hi, lo);
        oh1[4 * nd] = hi; ol1[4 * nd] = lo;
        split2(oacc[nd][2] * inv1, oacc[nd][3] * inv1, hi, lo);
        oh2[4 * nd] = hi; ol2[4 * nd] = lo;
    }
}

// ---------------------------------------------------------------------------
// Stage 3: out = att @ W^T + bias. CTA tile 128x128, 8 warps (4m x 2n),
// warp tile m32 x n64, K-chunks of 32. 2-stage cp.async, 32KB/stage = 64KB,
// __launch_bounds__(256,2) -> 2 CTAs/SM, 4 warps/SMSP.
// ---------------------------------------------------------------------------
#define OGS_AH 0
#define OGS_AL 8192
#define OGS_BH 16384
#define OGS_BL 24576
#define OG_STAGE 32768
#define OG_SMEM  65536

__global__ __launch_bounds__(256, 2) void gemm_mma(const float* __restrict__ bias,
                                                   float* __restrict__ out) {
    extern __shared__ char smp[];
    const uint32_t sb = smem_u32(smp);
    const int tid = threadIdx.x;
    const int w = tid >> 5, lane = tid & 31;
    const int wy = w >> 1, wx = w & 1;
    const int bm = blockIdx.y * 128, bn = blockIdx.x * 128;

    const __nv_bfloat16* Ah = g_att_hi;
    const __nv_bfloat16* Al = g_att_lo;
    const __nv_bfloat16* Bh = g_w_hi;
    const __nv_bfloat16* Bl = g_w_lo;

    float acc[2][8][4];
    #pragma unroll
    for (int mi = 0; mi < 2; mi++)
        #pragma unroll
        for (int j = 0; j < 8; j++)
            #pragma unroll
            for (int rr = 0; rr < 4; rr++) acc[mi][j][rr] = 0.0f;

    // chunk loader: 32KB per k-chunk (k=32) via cp.async into stage base ss
    auto issue_chunk = [&](int kc, uint32_t ss) {
        const int kw = kc * 32;
        #pragma unroll
        for (int i = 0; i < 2; i++) {
            int idx = tid + i * 256;          // 512 slots: 128 rows x 4 chunks
            int row = idx >> 2, c = idx & 3;
            uint32_t sw = swz32(row, c);
            cpa16(ss + OGS_AH + sw, Ah + (size_t)(bm + row) * EMB + kw + c * 8);
            cpa16(ss + OGS_AL + sw, Al + (size_t)(bm + row) * EMB + kw + c * 8);
            cpa16(ss + OGS_BH + sw, Bh + (size_t)(bn + row) * EMB + kw + c * 8);
            cpa16(ss + OGS_BL + sw, Bl + (size_t)(bn + row) * EMB + kw + c * 8);
        }
        CP_COMMIT();
    };

    issue_chunk(0, sb);

    for (int kc = 0; kc < 32; kc++) {
        const uint32_t ss  = sb + (kc & 1) * OG_STAGE;
        const uint32_t ssn = sb + ((kc + 1) & 1) * OG_STAGE;

        CP_WAIT0();
        __syncthreads();
        if (kc + 1 < 32) issue_chunk(kc + 1, ssn);

        #pragma unroll
        for (int kk = 0; kk < 2; kk++) {
            uint32_t ah0[4], al0[4], ah1[4], al1[4];
            uint32_t ch = 2 * kk + (lane >> 4);
            ldsm4(ah0, ss + OGS_AH + swz32(32 * wy + (lane & 15),      ch));
            ldsm4(al0, ss + OGS_AL + swz32(32 * wy + (lane & 15),      ch));
            ldsm4(ah1, ss + OGS_AH + swz32(32 * wy + 16 + (lane & 15), ch));
            ldsm4(al1, ss + OGS_AL + swz32(32 * wy + 16 + (lane & 15), ch));
            #pragma unroll
            for (int np = 0; np < 4; np++) {
                uint32_t bh4[4], bl4[4];
                uint32_t row = 64 * wx + 16 * np + (lane & 15);
                ldsm4(bh4, ss + OGS_BH + swz32(row, ch));
                ldsm4(bl4, ss + OGS_BL + swz32(row, ch));
                uint32_t b0h[2] = { bh4[0], bh4[2] }, b1h[2] = { bh4[1], bh4[3] };
                uint32_t b0l[2] = { bl4[0], bl4[2] }, b1l[2] = { bl4[1], bl4[3] };
                // round-major: hh over 4 accs, then lh, then hl (per-acc order kept)
                mma16816(acc[0][2 * np],     ah0, b0h);
                mma16816(acc[0][2 * np + 1], ah0, b1h);
                mma16816(acc[1][2 * np],     ah1, b0h);
                mma16816(acc[1][2 * np + 1], ah1, b1h);
                mma16816(acc[0][2 * np],     al0, b0h);
                mma16816(acc[0][2 * np + 1], al0, b1h);
                mma16816(acc[1][2 * np],     al1, b0h);
                mma16816(acc[1][2 * np + 1], al1, b1h);
                mma16816(acc[0][2 * np],     ah0, b0l);
                mma16816(acc[0][2 * np + 1], ah0, b1l);
                mma16816(acc[1][2 * np],     ah1, b0l);
                mma16816(acc[1][2 * np + 1], ah1, b1l);
            }
        }
    }

    #pragma unroll
    for (int mi = 0; mi < 2; mi++) {
        int r = bm + 32 * wy + 16 * mi + (lane >> 2);
        #pragma unroll
        for (int nt = 0; nt < 8; nt++) {
            int col = bn + 64 * wx + 8 * nt + 2 * (lane & 3);
            float bv0 = __ldg(bias + col), bv1 = __ldg(bias + col + 1);
            float2 v0, v1;
            v0.x = acc[mi][nt][0] + bv0; v0.y = acc[mi][nt][1] + bv1;
            v1.x = acc[mi][nt][2] + bv0; v1.y = acc[mi][nt][3] + bv1;
            *(float2*)(out + (size_t)r * EMB + col)       = v0;
            *(float2*)(out + (size_t)(r + 8) * EMB + col) = v1;
        }
    }
}

// ---------------------------------------------------------------------------
extern "C" void kernel_launch(void* const* d_in, const int* in_sizes, int n_in,
                              void* d_out, int out_size) {
    const float* x     = (const float*)d_in[0];   // [4,2048,1024]
    const float* theta = (const float*)d_in[1];   // [16,64]
    const float* w_out = (const float*)d_in[2];   // [1024,1024]
    const float* b_out = (const float*)d_in[3];   // [1024]
    float* out = (float*)d_out;                   // [4,2048,1024]

    cudaFuncSetAttribute(attn_mma, cudaFuncAttributeMaxDynamicSharedMemorySize, A_SMEM);
    cudaFuncSetAttribute(gemm_mma, cudaFuncAttributeMaxDynamicSharedMemorySize, OG_SMEM);

    qkv_kernel<<<(BATCH * SEQ * EMB) / 256, 256>>>(x, theta);
    wsplit_kernel<<<(EMB * EMB) / 256, 256>>>(w_out);
    attn_mma<<<BATCH * HEADS * (SEQ / 128), 256, A_SMEM>>>();
    dim3 ggrid(EMB / 128, (BATCH * SEQ) / 128);
    gemm_mma<<<ggrid, 256, OG_SMEM>>>(b_out, out);
}

// round 14
// speedup vs baseline: 4.2633x; 1.3973x over previous
#include <cuda_runtime.h>
#include <cuda_fp16.h>
#include <cstdint>

#define BATCH 4
#define SEQ   2048
#define EMB   1024
#define HEADS 16
#define DK    64

// ---------------- device scratch (no cudaMalloc allowed) --------------------
// fp16 asymmetric split: A-side operands keep hi+lo residual, B-side hi only.
__device__ __half g_qkv_hi[(size_t)BATCH * HEADS * SEQ * DK];
__device__ __half g_qkv_lo[(size_t)BATCH * HEADS * SEQ * DK];
__device__ __half g_att_hi[(size_t)BATCH * SEQ * EMB];
__device__ __half g_att_lo[(size_t)BATCH * SEQ * EMB];
__device__ __half g_w_hi[(size_t)EMB * EMB];

// ---------------- helpers ---------------------------------------------------
__device__ __forceinline__ uint32_t smem_u32(const void* p) {
    uint32_t a;
    asm("{ .reg .u64 t; cvta.to.shared.u64 t, %1; cvt.u32.u64 %0, t; }" : "=r"(a) : "l"(p));
    return a;
}

// 128B rows (64 fp16): 8 chunks of 16B, XOR swizzle -> conflict-free ldmatrix
__device__ __forceinline__ uint32_t swz(uint32_t row, uint32_t chunk) {
    return row * 128u + ((chunk ^ (row & 7u)) * 16u);
}
// 64B rows (32 fp16): 4 chunks of 16B; 8 ldmatrix rows hit 8 distinct 16B slots
__device__ __forceinline__ uint32_t swz32(uint32_t row, uint32_t chunk) {
    return row * 64u + ((chunk ^ ((row >> 1) & 3u)) * 16u);
}

__device__ __forceinline__ void ldsm4(uint32_t* r, uint32_t addr) {
    asm volatile("ldmatrix.sync.aligned.m8n8.x4.shared.b16 {%0,%1,%2,%3}, [%4];"
        : "=r"(r[0]), "=r"(r[1]), "=r"(r[2]), "=r"(r[3]) : "r"(addr));
}
__device__ __forceinline__ void ldsm4t(uint32_t* r, uint32_t addr) {
    asm volatile("ldmatrix.sync.aligned.m8n8.x4.trans.shared.b16 {%0,%1,%2,%3}, [%4];"
        : "=r"(r[0]), "=r"(r[1]), "=r"(r[2]), "=r"(r[3]) : "r"(addr));
}

// D = A(f16) * B(f16) + D(f32);  m16n8k16 row.col
__device__ __forceinline__ void mma16816(float* c, const uint32_t* a, const uint32_t* b) {
    asm volatile("mma.sync.aligned.m16n8k16.row.col.f32.f16.f16.f32 "
        "{%0,%1,%2,%3}, {%4,%5,%6,%7}, {%8,%9}, {%0,%1,%2,%3};"
        : "+f"(c[0]), "+f"(c[1]), "+f"(c[2]), "+f"(c[3])
        : "r"(a[0]), "r"(a[1]), "r"(a[2]), "r"(a[3]), "r"(b[0]), "r"(b[1]));
}

// async copy 16B global -> shared
__device__ __forceinline__ void cpa16(uint32_t saddr, const void* gaddr) {
    asm volatile("cp.async.cg.shared.global [%0], [%1], 16;" :: "r"(saddr), "l"(gaddr));
}
#define CP_COMMIT() asm volatile("cp.async.commit_group;" ::: "memory")
#define CP_WAIT0()  asm volatile("cp.async.wait_group 0;" ::: "memory")

// exp(s * 0.125) via exp2 polynomial on the FMA pipe (no MUFU).
__device__ __forceinline__ float exp_scaled(float s) {
    const float C = 0.18033688011f;           // 0.125 * log2(e)
    float t = s * C;
    float z = t + 12582912.0f;                // 1.5 * 2^23 magic
    int   i = __float_as_int(z);
    float fi = z - 12582912.0f;
    float f = t - fi;
    float p = 1.33335581e-3f;
    p = fmaf(p, f, 9.61812910e-3f);
    p = fmaf(p, f, 5.55041087e-2f);
    p = fmaf(p, f, 2.40226512e-1f);
    p = fmaf(p, f, 6.93147182e-1f);
    p = fmaf(p, f, 1.0f);
    return __int_as_float(__float_as_int(p) + (i << 23));
}

// pack two floats into f16x2 hi word + f16x2 residual word (a -> low half)
__device__ __forceinline__ void split2h(float a, float b, uint32_t& hi, uint32_t& lo) {
    __half2 h2 = __floats2half2_rn(a, b);        // x(lo)=a, y(hi)=b
    float2 f2 = __half22float2(h2);
    __half2 l2 = __floats2half2_rn(a - f2.x, b - f2.y);
    hi = *(uint32_t*)&h2;
    lo = *(uint32_t*)&l2;
}

// ---------------------------------------------------------------------------
// Stage 1: qkv split = cos(x + theta) -> f16 hi + f16 lo residual
// ---------------------------------------------------------------------------
__global__ __launch_bounds__(256) void qkv_kernel(const float* __restrict__ x,
                                                  const float* __restrict__ theta) {
    int idx = blockIdx.x * 256 + threadIdx.x;            // over B*S*E
    int e = idx & (EMB - 1);
    int s = (idx >> 10) & (SEQ - 1);
    int b = idx >> 21;
    int h = e >> 6, d = e & (DK - 1);
    float v = cosf(x[idx] + theta[e]);
    size_t o = ((((size_t)b * HEADS + h) * SEQ) + s) * DK + d;
    __half hi = __float2half_rn(v);
    g_qkv_hi[o] = hi;
    g_qkv_lo[o] = __float2half_rn(v - __half2float(hi));
}

__global__ __launch_bounds__(256) void wsplit_kernel(const float* __restrict__ w) {
    int idx = blockIdx.x * 256 + threadIdx.x;
    g_w_hi[idx] = __float2half_rn(w[idx]);
}

// ---------------------------------------------------------------------------
// Stage 2: attention. CTA = 128 q rows of one (b,h). 8 warps x m16.
// smem: Q hi/lo [128][64] (32KB) + 2-stage K-hi ring (2 x 8KB) = 48KB
// K side is single fp16 (no residual): 2 MMAs per step instead of 3.
// ---------------------------------------------------------------------------
#define AQ_H 0
#define AQ_L 16384
#define AK0  32768      // stage 0: K hi only, 8KB
#define AK1  40960      // stage 1
#define A_SMEM 49152

__global__ __launch_bounds__(256, 2) void attn_mma() {
    extern __shared__ char smp[];
    const uint32_t sb = smem_u32(smp);
    const int tid = threadIdx.x;
    const int w = tid >> 5, lane = tid & 31;
    const int bid = blockIdx.x;                 // B*H*16
    const int qt = bid & 15, bh = bid >> 4;
    const int b = bh >> 4, h = bh & 15;
    const int q0 = qt * 128;

    const __half* qh_base = g_qkv_hi + (size_t)bh * SEQ * DK;
    const __half* ql_base = g_qkv_lo + (size_t)bh * SEQ * DK;

    // per-thread K-tile slots: 64 rows x 8 chunks = 512 chunks, 2 per thread
    const int lrow0 = tid >> 3,          lc0 = tid & 7;   // rows 0..31
    const int lrow1 = (tid + 256) >> 3,  lc1 = tid & 7;   // rows 32..63
    const uint32_t sw0 = swz(lrow0, lc0), sw1 = swz(lrow1, lc1);

    // prologue: issue K tile 0 (hi only) into stage 0
    cpa16(sb + AK0 + sw0, qh_base + (size_t)lrow0 * DK + lc0 * 8);
    cpa16(sb + AK0 + sw1, qh_base + (size_t)lrow1 * DK + lc1 * 8);
    CP_COMMIT();

    // stage Q tile [128][64] hi/lo (swizzled), overlaps with tile-0 cp.async
    #pragma unroll
    for (int i = 0; i < 4; i++) {
        int idx = tid + i * 256;
        int row = idx >> 3, c = idx & 7;
        *(uint4*)(smp + AQ_H + swz(row, c)) =
            *(const uint4*)(qh_base + (size_t)(q0 + row) * DK + c * 8);
        *(uint4*)(smp + AQ_L + swz(row, c)) =
            *(const uint4*)(ql_base + (size_t)(q0 + row) * DK + c * 8);
    }
    __syncthreads();

    // Q fragments: kk = k16 group (d dim), 4 regs each, hi + lo
    uint32_t qh[4][4], ql[4][4];
    #pragma unroll
    for (int kk = 0; kk < 4; kk++) {
        ldsm4(qh[kk], sb + AQ_H + swz(16 * w + (lane & 15), 2 * kk + (lane >> 4)));
        ldsm4(ql[kk], sb + AQ_L + swz(16 * w + (lane & 15), 2 * kk + (lane >> 4)));
    }

    float oacc[8][4];
    #pragma unroll
    for (int j = 0; j < 8; j++)
        #pragma unroll
        for (int r = 0; r < 4; r++) oacc[j][r] = 0.0f;
    float den0 = 0.0f, den1 = 0.0f;

    for (int t = 0; t < 32; t++) {
        const uint32_t kb  = (t & 1) ? AK1 : AK0;
        const uint32_t kbn = (t & 1) ? AK0 : AK1;

        CP_WAIT0();            // tile t resident
        __syncthreads();       // all warps done with stage kbn

        if (t + 1 < 32) {      // prefetch tile t+1 (hi only)
            const __half* gh = qh_base + (size_t)(t + 1) * 64 * DK;
            cpa16(sb + kbn + sw0, gh + (size_t)lrow0 * DK + lc0 * 8);
            cpa16(sb + kbn + sw1, gh + (size_t)lrow1 * DK + lc1 * 8);
            CP_COMMIT();
        }

        const uint32_t kH = sb + kb;

        // ---- S = (Qh + Ql) @ Kh^T : 2 MMAs per acc group ----
        float sacc[8][4];
        #pragma unroll
        for (int j = 0; j < 8; j++)
            #pragma unroll
            for (int r = 0; r < 4; r++) sacc[j][r] = 0.0f;

        #pragma unroll
        for (int kk = 0; kk < 4; kk++) {
            #pragma unroll
            for (int np = 0; np < 4; np++) {
                uint32_t bh4[4];
                uint32_t row = 16 * np + (lane & 15), ch = 2 * kk + (lane >> 4);
                ldsm4(bh4, kH + swz(row, ch));
                uint32_t b0h[2] = { bh4[0], bh4[2] }, b1h[2] = { bh4[1], bh4[3] };
                mma16816(sacc[2 * np],     qh[kk], b0h);
                mma16816(sacc[2 * np + 1], qh[kk], b1h);
                mma16816(sacc[2 * np],     ql[kk], b0h);
                mma16816(sacc[2 * np + 1], ql[kk], b1h);
            }
        }

        // ---- exp + denominator (no max pass; |S|<=8) ----
        #pragma unroll
        for (int j = 0; j < 8; j++) {
            sacc[j][0] = exp_scaled(sacc[j][0]);
            sacc[j][1] = exp_scaled(sacc[j][1]);
            sacc[j][2] = exp_scaled(sacc[j][2]);
            sacc[j][3] = exp_scaled(sacc[j][3]);
            den0 += sacc[j][0] + sacc[j][1];
            den1 += sacc[j][2] + sacc[j][3];
        }

        // ---- P: repack S accumulators directly as A fragments (hi/lo) ----
        uint32_t ph[4][4], pl[4][4];
        #pragma unroll
        for (int kk = 0; kk < 4; kk++) {
            split2h(sacc[2 * kk][0],     sacc[2 * kk][1],     ph[kk][0], pl[kk][0]);
            split2h(sacc[2 * kk][2],     sacc[2 * kk][3],     ph[kk][1], pl[kk][1]);
            split2h(sacc[2 * kk + 1][0], sacc[2 * kk + 1][1], ph[kk][2], pl[kk][2]);
            split2h(sacc[2 * kk + 1][2], sacc[2 * kk + 1][3], ph[kk][3], pl[kk][3]);
        }

        // ---- O += (Ph + Pl) @ Vh  (V^T via ldmatrix.trans on the K tile) ----
        #pragma unroll
        for (int kk = 0; kk < 4; kk++) {
            #pragma unroll
            for (int ndp = 0; ndp < 4; ndp++) {
                uint32_t vh4[4];
                uint32_t row = 16 * kk + (lane & 7) + ((lane >> 3) & 1) * 8;
                uint32_t ch  = 2 * ndp + (lane >> 4);
                ldsm4t(vh4, kH + swz(row, ch));
                uint32_t v0h[2] = { vh4[0], vh4[1] }, v1h[2] = { vh4[2], vh4[3] };
                mma16816(oacc[2 * ndp],     ph[kk], v0h);
                mma16816(oacc[2 * ndp + 1], ph[kk], v1h);
                mma16816(oacc[2 * ndp],     pl[kk], v0h);
                mma16816(oacc[2 * ndp + 1], pl[kk], v1h);
            }
        }
    }

    // denominator: quad-reduce (lanes 4r..4r+3 hold disjoint column subsets)
    den0 += __shfl_xor_sync(0xffffffffu, den0, 1);
    den0 += __shfl_xor_sync(0xffffffffu, den0, 2);
    den1 += __shfl_xor_sync(0xffffffffu, den1, 1);
    den1 += __shfl_xor_sync(0xffffffffu, den1, 2);
    float inv0 = 1.0f / den0, inv1 = 1.0f / den1;

    int r = q0 + 16 * w + (lane >> 2);
    uint32_t* oh1 = (uint32_t*)g_att_hi + ((size_t)b * SEQ + r) * 512 + h * 32 + (lane & 3);
    uint32_t* ol1 = (uint32_t*)g_att_lo + ((size_t)b * SEQ + r) * 512 + h * 32 + (lane & 3);
    uint32_t* oh2 = (uint32_t*)g_att_hi + ((size_t)b * SEQ + r + 8) * 512 + h * 32 + (lane & 3);
    uint32_t* ol2 = (uint32_t*)g_att_lo + ((size_t)b * SEQ + r + 8) * 512 + h * 32 + (lane & 3);
    #pragma unroll
    for (int nd = 0; nd < 8; nd++) {
        uint32_t hi, lo;
        split2h(oacc[nd][0] * inv0, oacc[nd][1] * inv0, hi, lo);
        oh1[4 * nd] = hi; ol1[4 * nd] = lo;
        split2h(oacc[nd][2] * inv1, oacc[nd][3] * inv1, hi, lo);
        oh2[4 * nd] = hi; ol2[4 * nd] = lo;
    }
}

// ---------------------------------------------------------------------------
// Stage 3: out = att @ W^T + bias. CTA tile 128x128, 8 warps (4m x 2n),
// warp tile m32 x n64, K-chunks of 32, W single-fp16 (no residual).
// 2-stage cp.async, 24KB/stage = 48KB, 2 CTAs/SM.
// ---------------------------------------------------------------------------
#define OGS_AH 0
#define OGS_AL 8192
#define OGS_BH 16384
#define OG_STAGE 24576
#define OG_SMEM  49152

__global__ __launch_bounds__(256, 2) void gemm_mma(const float* __restrict__ bias,
                                                   float* __restrict__ out) {
    extern __shared__ char smp[];
    const uint32_t sb = smem_u32(smp);
    const int tid = threadIdx.x;
    const int w = tid >> 5, lane = tid & 31;
    const int wy = w >> 1, wx = w & 1;
    const int bm = blockIdx.y * 128, bn = blockIdx.x * 128;

    const __half* Ah = g_att_hi;
    const __half* Al = g_att_lo;
    const __half* Bh = g_w_hi;

    float acc[2][8][4];
    #pragma unroll
    for (int mi = 0; mi < 2; mi++)
        #pragma unroll
        for (int j = 0; j < 8; j++)
            #pragma unroll
            for (int rr = 0; rr < 4; rr++) acc[mi][j][rr] = 0.0f;

    // chunk loader: k=32 chunk -> Ah/Al/Bh, 512 16B-chunks each, 2 per thread
    auto issue_chunk = [&](int kc, uint32_t ss) {
        const int kw = kc * 32;
        #pragma unroll
        for (int i = 0; i < 2; i++) {
            int idx = tid + i * 256;          // 512 slots: 128 rows x 4 chunks
            int row = idx >> 2, c = idx & 3;
            uint32_t sw = swz32(row, c);
            cpa16(ss + OGS_AH + sw, Ah + (size_t)(bm + row) * EMB + kw + c * 8);
            cpa16(ss + OGS_AL + sw, Al + (size_t)(bm + row) * EMB + kw + c * 8);
            cpa16(ss + OGS_BH + sw, Bh + (size_t)(bn + row) * EMB + kw + c * 8);
        }
        CP_COMMIT();
    };

    issue_chunk(0, sb);

    for (int kc = 0; kc < 32; kc++) {
        const uint32_t ss  = sb + (kc & 1) * OG_STAGE;
        const uint32_t ssn = sb + ((kc + 1) & 1) * OG_STAGE;

        CP_WAIT0();
        __syncthreads();
        if (kc + 1 < 32) issue_chunk(kc + 1, ssn);

        #pragma unroll
        for (int kk = 0; kk < 2; kk++) {
            uint32_t ah0[4], al0[4], ah1[4], al1[4];
            uint32_t ch = 2 * kk + (lane >> 4);
            ldsm4(ah0, ss + OGS_AH + swz32(32 * wy + (lane & 15),      ch));
            ldsm4(al0, ss + OGS_AL + swz32(32 * wy + (lane & 15),      ch));
            ldsm4(ah1, ss + OGS_AH + swz32(32 * wy + 16 + (lane & 15), ch));
            ldsm4(al1, ss + OGS_AL + swz32(32 * wy + 16 + (lane & 15), ch));
            #pragma unroll
            for (int np = 0; np < 4; np++) {
                uint32_t bh4[4];
                uint32_t row = 64 * wx + 16 * np + (lane & 15);
                ldsm4(bh4, ss + OGS_BH + swz32(row, ch));
                uint32_t b0h[2] = { bh4[0], bh4[2] }, b1h[2] = { bh4[1], bh4[3] };
                // round-major across accs; (Ah + Al) * Bh
                mma16816(acc[0][2 * np],     ah0, b0h);
                mma16816(acc[0][2 * np + 1], ah0, b1h);
                mma16816(acc[1][2 * np],     ah1, b0h);
                mma16816(acc[1][2 * np + 1], ah1, b1h);
                mma16816(acc[0][2 * np],     al0, b0h);
                mma16816(acc[0][2 * np + 1], al0, b1h);
                mma16816(acc[1][2 * np],     al1, b0h);
                mma16816(acc[1][2 * np + 1], al1, b1h);
            }
        }
    }

    #pragma unroll
    for (int mi = 0; mi < 2; mi++) {
        int r = bm + 32 * wy + 16 * mi + (lane >> 2);
        #pragma unroll
        for (int nt = 0; nt < 8; nt++) {
            int col = bn + 64 * wx + 8 * nt + 2 * (lane & 3);
            float bv0 = __ldg(bias + col), bv1 = __ldg(bias + col + 1);
            float2 v0, v1;
            v0.x = acc[mi][nt][0] + bv0; v0.y = acc[mi][nt][1] + bv1;
            v1.x = acc[mi][nt][2] + bv0; v1.y = acc[mi][nt][3] + bv1;
            *(float2*)(out + (size_t)r * EMB + col)       = v0;
            *(float2*)(out + (size_t)(r + 8) * EMB + col) = v1;
        }
    }
}

// ---------------------------------------------------------------------------
extern "C" void kernel_launch(void* const* d_in, const int* in_sizes, int n_in,
                              void* d_out, int out_size) {
    const float* x     = (const float*)d_in[0];   // [4,2048,1024]
    const float* theta = (const float*)d_in[1];   // [16,64]
    const float* w_out = (const float*)d_in[2];   // [1024,1024]
    const float* b_out = (const float*)d_in[3];   // [1024]
    float* out = (float*)d_out;                   // [4,2048,1024]

    cudaFuncSetAttribute(attn_mma, cudaFuncAttributeMaxDynamicSharedMemorySize, A_SMEM);
    cudaFuncSetAttribute(gemm_mma, cudaFuncAttributeMaxDynamicSharedMemorySize, OG_SMEM);

    qkv_kernel<<<(BATCH * SEQ * EMB) / 256, 256>>>(x, theta);
    wsplit_kernel<<<(EMB * EMB) / 256, 256>>>(w_out);
    attn_mma<<<BATCH * HEADS * (SEQ / 128), 256, A_SMEM>>>();
    dim3 ggrid(EMB / 128, (BATCH * SEQ) / 128);
    gemm_mma<<<ggrid, 256, OG_SMEM>>>(b_out, out);
}

// round 15
// speedup vs baseline: 6.3861x; 1.4979x over previous
#include <cuda_runtime.h>
#include <cuda_fp16.h>
#include <cstdint>

#define BATCH 4
#define SEQ   2048
#define EMB   1024
#define HEADS 16
#define DK    64

// ---------------- device scratch (no cudaMalloc allowed) --------------------
// qkv: single fp16 (softmax averaging suppresses Q/K/V residual error).
// att: fp16 hi+lo (out-projection error is NOT suppressed -> keep residual).
__device__ __half g_qkv_hi[(size_t)BATCH * HEADS * SEQ * DK];
__device__ __half g_att_hi[(size_t)BATCH * SEQ * EMB];
__device__ __half g_att_lo[(size_t)BATCH * SEQ * EMB];
__device__ __half g_w_hi[(size_t)EMB * EMB];

// ---------------- helpers ---------------------------------------------------
__device__ __forceinline__ uint32_t smem_u32(const void* p) {
    uint32_t a;
    asm("{ .reg .u64 t; cvta.to.shared.u64 t, %1; cvt.u32.u64 %0, t; }" : "=r"(a) : "l"(p));
    return a;
}

// 128B rows (64 fp16): 8 chunks of 16B, XOR swizzle -> conflict-free ldmatrix
__device__ __forceinline__ uint32_t swz(uint32_t row, uint32_t chunk) {
    return row * 128u + ((chunk ^ (row & 7u)) * 16u);
}

__device__ __forceinline__ void ldsm4(uint32_t* r, uint32_t addr) {
    asm volatile("ldmatrix.sync.aligned.m8n8.x4.shared.b16 {%0,%1,%2,%3}, [%4];"
        : "=r"(r[0]), "=r"(r[1]), "=r"(r[2]), "=r"(r[3]) : "r"(addr));
}
__device__ __forceinline__ void ldsm4t(uint32_t* r, uint32_t addr) {
    asm volatile("ldmatrix.sync.aligned.m8n8.x4.trans.shared.b16 {%0,%1,%2,%3}, [%4];"
        : "=r"(r[0]), "=r"(r[1]), "=r"(r[2]), "=r"(r[3]) : "r"(addr));
}

// D = A(f16) * B(f16) + D(f32);  m16n8k16 row.col
__device__ __forceinline__ void mma16816(float* c, const uint32_t* a, const uint32_t* b) {
    asm volatile("mma.sync.aligned.m16n8k16.row.col.f32.f16.f16.f32 "
        "{%0,%1,%2,%3}, {%4,%5,%6,%7}, {%8,%9}, {%0,%1,%2,%3};"
        : "+f"(c[0]), "+f"(c[1]), "+f"(c[2]), "+f"(c[3])
        : "r"(a[0]), "r"(a[1]), "r"(a[2]), "r"(a[3]), "r"(b[0]), "r"(b[1]));
}

// async copy 16B global -> shared
__device__ __forceinline__ void cpa16(uint32_t saddr, const void* gaddr) {
    asm volatile("cp.async.cg.shared.global [%0], [%1], 16;" :: "r"(saddr), "l"(gaddr));
}
#define CP_COMMIT() asm volatile("cp.async.commit_group;" ::: "memory")
#define CP_WAIT0()  asm volatile("cp.async.wait_group 0;" ::: "memory")

// exp(s * 0.125) via exp2 degree-4 polynomial on the FMA pipe (no MUFU).
__device__ __forceinline__ float exp_scaled(float s) {
    const float C = 0.18033688011f;            // 0.125 * log2(e)
    const float M = 12582912.0f;               // 1.5 * 2^23 magic
    float z = fmaf(s, C, M);
    int   i = __float_as_int(z);
    float fi = z - M;
    float f = fmaf(s, C, -fi);                 // f in [-0.5, 0.5]
    float p = 9.6179e-3f;
    p = fmaf(p, f, 5.5503e-2f);
    p = fmaf(p, f, 2.4023e-1f);
    p = fmaf(p, f, 6.93147e-1f);
    p = fmaf(p, f, 1.0f);
    return __int_as_float(__float_as_int(p) + (i << 23));
}

// pack two floats into one f16x2 word (a -> low half)
__device__ __forceinline__ uint32_t pack2h(float a, float b) {
    __half2 h2 = __floats2half2_rn(a, b);
    return *(uint32_t*)&h2;
}
// pack two floats into f16x2 hi word + f16x2 residual word
__device__ __forceinline__ void split2h(float a, float b, uint32_t& hi, uint32_t& lo) {
    __half2 h2 = __floats2half2_rn(a, b);
    float2 f2 = __half22float2(h2);
    __half2 l2 = __floats2half2_rn(a - f2.x, b - f2.y);
    hi = *(uint32_t*)&h2;
    lo = *(uint32_t*)&l2;
}

// ---------------------------------------------------------------------------
// Stage 1: qkv = cos(x + theta) -> single f16
// ---------------------------------------------------------------------------
__global__ __launch_bounds__(256) void qkv_kernel(const float* __restrict__ x,
                                                  const float* __restrict__ theta) {
    int idx = blockIdx.x * 256 + threadIdx.x;            // over B*S*E
    int e = idx & (EMB - 1);
    int s = (idx >> 10) & (SEQ - 1);
    int b = idx >> 21;
    int h = e >> 6, d = e & (DK - 1);
    float v = cosf(x[idx] + theta[e]);
    size_t o = ((((size_t)b * HEADS + h) * SEQ) + s) * DK + d;
    g_qkv_hi[o] = __float2half_rn(v);
}

__global__ __launch_bounds__(256) void wsplit_kernel(const float* __restrict__ w) {
    int idx = blockIdx.x * 256 + threadIdx.x;
    g_w_hi[idx] = __float2half_rn(w[idx]);
}

// ---------------------------------------------------------------------------
// Stage 2: attention. CTA = 128 q rows of one (b,h). 8 warps x m16.
// S = Qh @ Kh^T (single fp16), PV = Ph @ Vh (single fp16).
// smem: Q hi [128][64] (16KB) + 2-stage K-hi ring (2 x 8KB) = 32KB
// ---------------------------------------------------------------------------
#define AQ_H 0
#define AK0  16384      // stage 0: K hi, 8KB
#define AK1  24576      // stage 1
#define A_SMEM 32768

__global__ __launch_bounds__(256, 2) void attn_mma() {
    extern __shared__ char smp[];
    const uint32_t sb = smem_u32(smp);
    const int tid = threadIdx.x;
    const int w = tid >> 5, lane = tid & 31;
    const int bid = blockIdx.x;                 // B*H*16
    const int qt = bid & 15, bh = bid >> 4;
    const int b = bh >> 4, h = bh & 15;
    const int q0 = qt * 128;

    const __half* qh_base = g_qkv_hi + (size_t)bh * SEQ * DK;

    // per-thread K-tile slots: 64 rows x 8 chunks = 512 chunks, 2 per thread
    const int lrow0 = tid >> 3,          lc0 = tid & 7;   // rows 0..31
    const int lrow1 = (tid + 256) >> 3,  lc1 = tid & 7;   // rows 32..63
    const uint32_t sw0 = swz(lrow0, lc0), sw1 = swz(lrow1, lc1);

    // prologue: issue K tile 0 into stage 0
    cpa16(sb + AK0 + sw0, qh_base + (size_t)lrow0 * DK + lc0 * 8);
    cpa16(sb + AK0 + sw1, qh_base + (size_t)lrow1 * DK + lc1 * 8);
    CP_COMMIT();

    // stage Q tile [128][64] (swizzled), overlaps with tile-0 cp.async
    #pragma unroll
    for (int i = 0; i < 2; i++) {
        int idx = tid + i * 256;
        int row = idx >> 2, c2 = (idx & 3) * 2;       // 2 chunks per slot
        *(uint4*)(smp + AQ_H + swz(row, c2)) =
            *(const uint4*)(qh_base + (size_t)(q0 + row) * DK + c2 * 8);
        *(uint4*)(smp + AQ_H + swz(row, c2 + 1)) =
            *(const uint4*)(qh_base + (size_t)(q0 + row) * DK + c2 * 8 + 8);
    }
    __syncthreads();

    // Q fragments: kk = k16 group (d dim), 4 regs each
    uint32_t qh[4][4];
    #pragma unroll
    for (int kk = 0; kk < 4; kk++)
        ldsm4(qh[kk], sb + AQ_H + swz(16 * w + (lane & 15), 2 * kk + (lane >> 4)));

    float oacc[8][4];
    #pragma unroll
    for (int j = 0; j < 8; j++)
        #pragma unroll
        for (int r = 0; r < 4; r++) oacc[j][r] = 0.0f;
    float den0 = 0.0f, den1 = 0.0f;

    for (int t = 0; t < 32; t++) {
        const uint32_t kb  = (t & 1) ? AK1 : AK0;
        const uint32_t kbn = (t & 1) ? AK0 : AK1;

        CP_WAIT0();            // tile t resident
        __syncthreads();       // all warps done with stage kbn

        if (t + 1 < 32) {      // prefetch tile t+1
            const __half* gh = qh_base + (size_t)(t + 1) * 64 * DK;
            cpa16(sb + kbn + sw0, gh + (size_t)lrow0 * DK + lc0 * 8);
            cpa16(sb + kbn + sw1, gh + (size_t)lrow1 * DK + lc1 * 8);
            CP_COMMIT();
        }

        const uint32_t kH = sb + kb;

        // ---- S = Qh @ Kh^T ----
        float sacc[8][4];
        #pragma unroll
        for (int j = 0; j < 8; j++)
            #pragma unroll
            for (int r = 0; r < 4; r++) sacc[j][r] = 0.0f;

        #pragma unroll
        for (int kk = 0; kk < 4; kk++) {
            #pragma unroll
            for (int np = 0; np < 4; np++) {
                uint32_t bh4[4];
                uint32_t row = 16 * np + (lane & 15), ch = 2 * kk + (lane >> 4);
                ldsm4(bh4, kH + swz(row, ch));
                uint32_t b0h[2] = { bh4[0], bh4[2] }, b1h[2] = { bh4[1], bh4[3] };
                mma16816(sacc[2 * np],     qh[kk], b0h);
                mma16816(sacc[2 * np + 1], qh[kk], b1h);
            }
        }

        // ---- exp + denominator (no max pass; |S|<=8) ----
        #pragma unroll
        for (int j = 0; j < 8; j++) {
            sacc[j][0] = exp_scaled(sacc[j][0]);
            sacc[j][1] = exp_scaled(sacc[j][1]);
            sacc[j][2] = exp_scaled(sacc[j][2]);
            sacc[j][3] = exp_scaled(sacc[j][3]);
            den0 += sacc[j][0] + sacc[j][1];
            den1 += sacc[j][2] + sacc[j][3];
        }

        // ---- P: pack S accumulators as fp16 A fragments (no residual) ----
        uint32_t ph[4][4];
        #pragma unroll
        for (int kk = 0; kk < 4; kk++) {
            ph[kk][0] = pack2h(sacc[2 * kk][0],     sacc[2 * kk][1]);
            ph[kk][1] = pack2h(sacc[2 * kk][2],     sacc[2 * kk][3]);
            ph[kk][2] = pack2h(sacc[2 * kk + 1][0], sacc[2 * kk + 1][1]);
            ph[kk][3] = pack2h(sacc[2 * kk + 1][2], sacc[2 * kk + 1][3]);
        }

        // ---- O += Ph @ Vh  (V^T via ldmatrix.trans on the K tile) ----
        #pragma unroll
        for (int kk = 0; kk < 4; kk++) {
            #pragma unroll
            for (int ndp = 0; ndp < 4; ndp++) {
                uint32_t vh4[4];
                uint32_t row = 16 * kk + (lane & 7) + ((lane >> 3) & 1) * 8;
                uint32_t ch  = 2 * ndp + (lane >> 4);
                ldsm4t(vh4, kH + swz(row, ch));
                uint32_t v0h[2] = { vh4[0], vh4[1] }, v1h[2] = { vh4[2], vh4[3] };
                mma16816(oacc[2 * ndp],     ph[kk], v0h);
                mma16816(oacc[2 * ndp + 1], ph[kk], v1h);
            }
        }
    }

    // denominator: quad-reduce (lanes 4r..4r+3 hold disjoint column subsets)
    den0 += __shfl_xor_sync(0xffffffffu, den0, 1);
    den0 += __shfl_xor_sync(0xffffffffu, den0, 2);
    den1 += __shfl_xor_sync(0xffffffffu, den1, 1);
    den1 += __shfl_xor_sync(0xffffffffu, den1, 2);
    float inv0 = 1.0f / den0, inv1 = 1.0f / den1;

    int r = q0 + 16 * w + (lane >> 2);
    uint32_t* oh1 = (uint32_t*)g_att_hi + ((size_t)b * SEQ + r) * 512 + h * 32 + (lane & 3);
    uint32_t* ol1 = (uint32_t*)g_att_lo + ((size_t)b * SEQ + r) * 512 + h * 32 + (lane & 3);
    uint32_t* oh2 = (uint32_t*)g_att_hi + ((size_t)b * SEQ + r + 8) * 512 + h * 32 + (lane & 3);
    uint32_t* ol2 = (uint32_t*)g_att_lo + ((size_t)b * SEQ + r + 8) * 512 + h * 32 + (lane & 3);
    #pragma unroll
    for (int nd = 0; nd < 8; nd++) {
        uint32_t hi, lo;
        split2h(oacc[nd][0] * inv0, oacc[nd][1] * inv0, hi, lo);
        oh1[4 * nd] = hi; ol1[4 * nd] = lo;
        split2h(oacc[nd][2] * inv1, oacc[nd][3] * inv1, hi, lo);
        oh2[4 * nd] = hi; ol2[4 * nd] = lo;
    }
}

// ---------------------------------------------------------------------------
// Stage 3: out = att @ W^T + bias. CTA tile 128x128, 8 warps (4m x 2n),
// warp tile m32 x n64, K-chunks of 64 (A hi+lo, W hi).
// 2-stage cp.async, 48KB/stage = 96KB, 2 CTAs/SM (192KB smem).
// ---------------------------------------------------------------------------
#define OGS_AH 0
#define OGS_AL 16384
#define OGS_BH 32768
#define OG_STAGE 49152
#define OG_SMEM  98304

__global__ __launch_bounds__(256, 2) void gemm_mma(const float* __restrict__ bias,
                                                   float* __restrict__ out) {
    extern __shared__ char smp[];
    const uint32_t sb = smem_u32(smp);
    const int tid = threadIdx.x;
    const int w = tid >> 5, lane = tid & 31;
    const int wy = w >> 1, wx = w & 1;
    const int bm = blockIdx.y * 128, bn = blockIdx.x * 128;

    const __half* Ah = g_att_hi;
    const __half* Al = g_att_lo;
    const __half* Bh = g_w_hi;

    float acc[2][8][4];
    #pragma unroll
    for (int mi = 0; mi < 2; mi++)
        #pragma unroll
        for (int j = 0; j < 8; j++)
            #pragma unroll
            for (int rr = 0; rr < 4; rr++) acc[mi][j][rr] = 0.0f;

    // chunk loader: k=64 chunk -> Ah/Al/Bh, 1024 16B-chunks each (128 rows x 8)
    auto issue_chunk = [&](int kc, uint32_t ss) {
        const int kw = kc * 64;
        #pragma unroll
        for (int i = 0; i < 4; i++) {
            int idx = tid + i * 256;          // 1024 slots: 128 rows x 8 chunks
            int row = idx >> 3, c = idx & 7;
            uint32_t sw = swz(row, c);
            cpa16(ss + OGS_AH + sw, Ah + (size_t)(bm + row) * EMB + kw + c * 8);
            cpa16(ss + OGS_AL + sw, Al + (size_t)(bm + row) * EMB + kw + c * 8);
            cpa16(ss + OGS_BH + sw, Bh + (size_t)(bn + row) * EMB + kw + c * 8);
        }
        CP_COMMIT();
    };

    issue_chunk(0, sb);

    for (int kc = 0; kc < 16; kc++) {
        const uint32_t ss  = sb + (kc & 1) * OG_STAGE;
        const uint32_t ssn = sb + ((kc + 1) & 1) * OG_STAGE;

        CP_WAIT0();
        __syncthreads();
        if (kc + 1 < 16) issue_chunk(kc + 1, ssn);

        #pragma unroll
        for (int kk = 0; kk < 4; kk++) {
            uint32_t ah0[4], al0[4], ah1[4], al1[4];
            uint32_t ch = 2 * kk + (lane >> 4);
            ldsm4(ah0, ss + OGS_AH + swz(32 * wy + (lane & 15),      ch));
            ldsm4(al0, ss + OGS_AL + swz(32 * wy + (lane & 15),      ch));
            ldsm4(ah1, ss + OGS_AH + swz(32 * wy + 16 + (lane & 15), ch));
            ldsm4(al1, ss + OGS_AL + swz(32 * wy + 16 + (lane & 15), ch));
            #pragma unroll
            for (int np = 0; np < 4; np++) {
                uint32_t bh4[4];
                uint32_t row = 64 * wx + 16 * np + (lane & 15);
                ldsm4(bh4, ss + OGS_BH + swz(row, ch));
                uint32_t b0h[2] = { bh4[0], bh4[2] }, b1h[2] = { bh4[1], bh4[3] };
                // round-major across accs; (Ah + Al) * Bh
                mma16816(acc[0][2 * np],     ah0, b0h);
                mma16816(acc[0][2 * np + 1], ah0, b1h);
                mma16816(acc[1][2 * np],     ah1, b0h);
                mma16816(acc[1][2 * np + 1], ah1, b1h);
                mma16816(acc[0][2 * np],     al0, b0h);
                mma16816(acc[0][2 * np + 1], al0, b1h);
                mma16816(acc[1][2 * np],     al1, b0h);
                mma16816(acc[1][2 * np + 1], al1, b1h);
            }
        }
    }

    #pragma unroll
    for (int mi = 0; mi < 2; mi++) {
        int r = bm + 32 * wy + 16 * mi + (lane >> 2);
        #pragma unroll
        for (int nt = 0; nt < 8; nt++) {
            int col = bn + 64 * wx + 8 * nt + 2 * (lane & 3);
            float bv0 = __ldg(bias + col), bv1 = __ldg(bias + col + 1);
            float2 v0, v1;
            v0.x = acc[mi][nt][0] + bv0; v0.y = acc[mi][nt][1] + bv1;
            v1.x = acc[mi][nt][2] + bv0; v1.y = acc[mi][nt][3] + bv1;
            *(float2*)(out + (size_t)r * EMB + col)       = v0;
            *(float2*)(out + (size_t)(r + 8) * EMB + col) = v1;
        }
    }
}

// ---------------------------------------------------------------------------
extern "C" void kernel_launch(void* const* d_in, const int* in_sizes, int n_in,
                              void* d_out, int out_size) {
    const float* x     = (const float*)d_in[0];   // [4,2048,1024]
    const float* theta = (const float*)d_in[1];   // [16,64]
    const float* w_out = (const float*)d_in[2];   // [1024,1024]
    const float* b_out = (const float*)d_in[3];   // [1024]
    float* out = (float*)d_out;                   // [4,2048,1024]

    cudaFuncSetAttribute(attn_mma, cudaFuncAttributeMaxDynamicSharedMemorySize, A_SMEM);
    cudaFuncSetAttribute(gemm_mma, cudaFuncAttributeMaxDynamicSharedMemorySize, OG_SMEM);

    qkv_kernel<<<(BATCH * SEQ * EMB) / 256, 256>>>(x, theta);
    wsplit_kernel<<<(EMB * EMB) / 256, 256>>>(w_out);
    attn_mma<<<BATCH * HEADS * (SEQ / 128), 256, A_SMEM>>>();
    dim3 ggrid(EMB / 128, (BATCH * SEQ) / 128);
    gemm_mma<<<ggrid, 256, OG_SMEM>>>(b_out, out);
}

// round 16
// speedup vs baseline: 7.4331x; 1.1640x over previous
#include <cuda_runtime.h>
#include <cuda_fp16.h>
#include <cstdint>

#define BATCH 4
#define SEQ   2048
#define EMB   1024
#define HEADS 16
#define DK    64

// ---------------- device scratch (no cudaMalloc allowed) --------------------
// qkv, att, w: single fp16. Measured error budget: softmax averaging suppresses
// qkv/P residuals; att fp16 rounding adds ~2.8e-4 unbiased -> total ~3.3e-4.
__device__ __half g_qkv_hi[(size_t)BATCH * HEADS * SEQ * DK];
__device__ __half g_att_hi[(size_t)BATCH * SEQ * EMB];
__device__ __half g_w_hi[(size_t)EMB * EMB];

// ---------------- helpers ---------------------------------------------------
__device__ __forceinline__ uint32_t smem_u32(const void* p) {
    uint32_t a;
    asm("{ .reg .u64 t; cvta.to.shared.u64 t, %1; cvt.u32.u64 %0, t; }" : "=r"(a) : "l"(p));
    return a;
}

// 128B rows (64 fp16): 8 chunks of 16B, XOR swizzle -> conflict-free ldmatrix
__device__ __forceinline__ uint32_t swz(uint32_t row, uint32_t chunk) {
    return row * 128u + ((chunk ^ (row & 7u)) * 16u);
}

__device__ __forceinline__ void ldsm4(uint32_t* r, uint32_t addr) {
    asm volatile("ldmatrix.sync.aligned.m8n8.x4.shared.b16 {%0,%1,%2,%3}, [%4];"
        : "=r"(r[0]), "=r"(r[1]), "=r"(r[2]), "=r"(r[3]) : "r"(addr));
}
__device__ __forceinline__ void ldsm4t(uint32_t* r, uint32_t addr) {
    asm volatile("ldmatrix.sync.aligned.m8n8.x4.trans.shared.b16 {%0,%1,%2,%3}, [%4];"
        : "=r"(r[0]), "=r"(r[1]), "=r"(r[2]), "=r"(r[3]) : "r"(addr));
}

// D = A(f16) * B(f16) + D(f32);  m16n8k16 row.col
__device__ __forceinline__ void mma16816(float* c, const uint32_t* a, const uint32_t* b) {
    asm volatile("mma.sync.aligned.m16n8k16.row.col.f32.f16.f16.f32 "
        "{%0,%1,%2,%3}, {%4,%5,%6,%7}, {%8,%9}, {%0,%1,%2,%3};"
        : "+f"(c[0]), "+f"(c[1]), "+f"(c[2]), "+f"(c[3])
        : "r"(a[0]), "r"(a[1]), "r"(a[2]), "r"(a[3]), "r"(b[0]), "r"(b[1]));
}

// async copy 16B global -> shared
__device__ __forceinline__ void cpa16(uint32_t saddr, const void* gaddr) {
    asm volatile("cp.async.cg.shared.global [%0], [%1], 16;" :: "r"(saddr), "l"(gaddr));
}
#define CP_COMMIT() asm volatile("cp.async.commit_group;" ::: "memory")
#define CP_WAIT0()  asm volatile("cp.async.wait_group 0;" ::: "memory")
#define CP_WAIT1()  asm volatile("cp.async.wait_group 1;" ::: "memory")

// exp(s * 0.125) via exp2 degree-4 polynomial on the FMA pipe (no MUFU).
__device__ __forceinline__ float exp_scaled(float s) {
    const float C = 0.18033688011f;            // 0.125 * log2(e)
    const float M = 12582912.0f;               // 1.5 * 2^23 magic
    float z = fmaf(s, C, M);
    int   i = __float_as_int(z);
    float fi = z - M;
    float f = fmaf(s, C, -fi);                 // f in [-0.5, 0.5]
    float p = 9.6179e-3f;
    p = fmaf(p, f, 5.5503e-2f);
    p = fmaf(p, f, 2.4023e-1f);
    p = fmaf(p, f, 6.93147e-1f);
    p = fmaf(p, f, 1.0f);
    return __int_as_float(__float_as_int(p) + (i << 23));
}

// pack two floats into one f16x2 word (a -> low half)
__device__ __forceinline__ uint32_t pack2h(float a, float b) {
    __half2 h2 = __floats2half2_rn(a, b);
    return *(uint32_t*)&h2;
}

// ---------------------------------------------------------------------------
// Stage 1: qkv = cos(x + theta) -> single f16
// ---------------------------------------------------------------------------
__global__ __launch_bounds__(256) void qkv_kernel(const float* __restrict__ x,
                                                  const float* __restrict__ theta) {
    int idx = blockIdx.x * 256 + threadIdx.x;            // over B*S*E
    int e = idx & (EMB - 1);
    int s = (idx >> 10) & (SEQ - 1);
    int b = idx >> 21;
    int h = e >> 6, d = e & (DK - 1);
    float v = cosf(x[idx] + theta[e]);
    size_t o = ((((size_t)b * HEADS + h) * SEQ) + s) * DK + d;
    g_qkv_hi[o] = __float2half_rn(v);
}

__global__ __launch_bounds__(256) void wsplit_kernel(const float* __restrict__ w) {
    int idx = blockIdx.x * 256 + threadIdx.x;
    g_w_hi[idx] = __float2half_rn(w[idx]);
}

// ---------------------------------------------------------------------------
// Stage 2: attention. CTA = 128 q rows of one (b,h). 8 warps x m16.
// S = Qh @ Kh^T, PV = Ph @ Vh (single fp16 everywhere; fp32 accum + softmax).
// smem: Q hi [128][64] (16KB) + 2-stage K-hi ring (2 x 8KB) = 32KB
// ---------------------------------------------------------------------------
#define AQ_H 0
#define AK0  16384      // stage 0: K hi, 8KB
#define AK1  24576      // stage 1
#define A_SMEM 32768

__global__ __launch_bounds__(256, 2) void attn_mma() {
    extern __shared__ char smp[];
    const uint32_t sb = smem_u32(smp);
    const int tid = threadIdx.x;
    const int w = tid >> 5, lane = tid & 31;
    const int bid = blockIdx.x;                 // B*H*16
    const int qt = bid & 15, bh = bid >> 4;
    const int b = bh >> 4, h = bh & 15;
    const int q0 = qt * 128;

    const __half* qh_base = g_qkv_hi + (size_t)bh * SEQ * DK;

    // per-thread K-tile slots: 64 rows x 8 chunks = 512 chunks, 2 per thread
    const int lrow0 = tid >> 3,          lc0 = tid & 7;   // rows 0..31
    const int lrow1 = (tid + 256) >> 3,  lc1 = tid & 7;   // rows 32..63
    const uint32_t sw0 = swz(lrow0, lc0), sw1 = swz(lrow1, lc1);

    // prologue: issue K tile 0 into stage 0
    cpa16(sb + AK0 + sw0, qh_base + (size_t)lrow0 * DK + lc0 * 8);
    cpa16(sb + AK0 + sw1, qh_base + (size_t)lrow1 * DK + lc1 * 8);
    CP_COMMIT();

    // stage Q tile [128][64] (swizzled), overlaps with tile-0 cp.async
    #pragma unroll
    for (int i = 0; i < 2; i++) {
        int idx = tid + i * 256;
        int row = idx >> 2, c2 = (idx & 3) * 2;       // 2 chunks per slot
        *(uint4*)(smp + AQ_H + swz(row, c2)) =
            *(const uint4*)(qh_base + (size_t)(q0 + row) * DK + c2 * 8);
        *(uint4*)(smp + AQ_H + swz(row, c2 + 1)) =
            *(const uint4*)(qh_base + (size_t)(q0 + row) * DK + c2 * 8 + 8);
    }
    __syncthreads();

    // Q fragments: kk = k16 group (d dim), 4 regs each
    uint32_t qh[4][4];
    #pragma unroll
    for (int kk = 0; kk < 4; kk++)
        ldsm4(qh[kk], sb + AQ_H + swz(16 * w + (lane & 15), 2 * kk + (lane >> 4)));

    float oacc[8][4];
    #pragma unroll
    for (int j = 0; j < 8; j++)
        #pragma unroll
        for (int r = 0; r < 4; r++) oacc[j][r] = 0.0f;
    float den0 = 0.0f, den1 = 0.0f;

    for (int t = 0; t < 32; t++) {
        const uint32_t kb  = (t & 1) ? AK1 : AK0;
        const uint32_t kbn = (t & 1) ? AK0 : AK1;

        CP_WAIT0();            // tile t resident
        __syncthreads();       // all warps done with stage kbn

        if (t + 1 < 32) {      // prefetch tile t+1
            const __half* gh = qh_base + (size_t)(t + 1) * 64 * DK;
            cpa16(sb + kbn + sw0, gh + (size_t)lrow0 * DK + lc0 * 8);
            cpa16(sb + kbn + sw1, gh + (size_t)lrow1 * DK + lc1 * 8);
            CP_COMMIT();
        }

        const uint32_t kH = sb + kb;

        // ---- S = Qh @ Kh^T ----
        float sacc[8][4];
        #pragma unroll
        for (int j = 0; j < 8; j++)
            #pragma unroll
            for (int r = 0; r < 4; r++) sacc[j][r] = 0.0f;

        #pragma unroll
        for (int kk = 0; kk < 4; kk++) {
            #pragma unroll
            for (int np = 0; np < 4; np++) {
                uint32_t bh4[4];
                uint32_t row = 16 * np + (lane & 15), ch = 2 * kk + (lane >> 4);
                ldsm4(bh4, kH + swz(row, ch));
                uint32_t b0h[2] = { bh4[0], bh4[2] }, b1h[2] = { bh4[1], bh4[3] };
                mma16816(sacc[2 * np],     qh[kk], b0h);
                mma16816(sacc[2 * np + 1], qh[kk], b1h);
            }
        }

        // ---- exp + denominator (no max pass; |S|<=8) ----
        #pragma unroll
        for (int j = 0; j < 8; j++) {
            sacc[j][0] = exp_scaled(sacc[j][0]);
            sacc[j][1] = exp_scaled(sacc[j][1]);
            sacc[j][2] = exp_scaled(sacc[j][2]);
            sacc[j][3] = exp_scaled(sacc[j][3]);
            den0 += sacc[j][0] + sacc[j][1];
            den1 += sacc[j][2] + sacc[j][3];
        }

        // ---- P: pack S accumulators as fp16 A fragments ----
        uint32_t ph[4][4];
        #pragma unroll
        for (int kk = 0; kk < 4; kk++) {
            ph[kk][0] = pack2h(sacc[2 * kk][0],     sacc[2 * kk][1]);
            ph[kk][1] = pack2h(sacc[2 * kk][2],     sacc[2 * kk][3]);
            ph[kk][2] = pack2h(sacc[2 * kk + 1][0], sacc[2 * kk + 1][1]);
            ph[kk][3] = pack2h(sacc[2 * kk + 1][2], sacc[2 * kk + 1][3]);
        }

        // ---- O += Ph @ Vh  (V^T via ldmatrix.trans on the K tile) ----
        #pragma unroll
        for (int kk = 0; kk < 4; kk++) {
            #pragma unroll
            for (int ndp = 0; ndp < 4; ndp++) {
                uint32_t vh4[4];
                uint32_t row = 16 * kk + (lane & 7) + ((lane >> 3) & 1) * 8;
                uint32_t ch  = 2 * ndp + (lane >> 4);
                ldsm4t(vh4, kH + swz(row, ch));
                uint32_t v0h[2] = { vh4[0], vh4[1] }, v1h[2] = { vh4[2], vh4[3] };
                mma16816(oacc[2 * ndp],     ph[kk], v0h);
                mma16816(oacc[2 * ndp + 1], ph[kk], v1h);
            }
        }
    }

    // denominator: quad-reduce (lanes 4r..4r+3 hold disjoint column subsets)
    den0 += __shfl_xor_sync(0xffffffffu, den0, 1);
    den0 += __shfl_xor_sync(0xffffffffu, den0, 2);
    den1 += __shfl_xor_sync(0xffffffffu, den1, 1);
    den1 += __shfl_xor_sync(0xffffffffu, den1, 2);
    float inv0 = 1.0f / den0, inv1 = 1.0f / den1;

    int r = q0 + 16 * w + (lane >> 2);
    uint32_t* oh1 = (uint32_t*)g_att_hi + ((size_t)b * SEQ + r) * 512 + h * 32 + (lane & 3);
    uint32_t* oh2 = (uint32_t*)g_att_hi + ((size_t)b * SEQ + r + 8) * 512 + h * 32 + (lane & 3);
    #pragma unroll
    for (int nd = 0; nd < 8; nd++) {
        oh1[4 * nd] = pack2h(oacc[nd][0] * inv0, oacc[nd][1] * inv0);
        oh2[4 * nd] = pack2h(oacc[nd][2] * inv1, oacc[nd][3] * inv1);
    }
}

// ---------------------------------------------------------------------------
// Stage 3: out = att @ W^T + bias. CTA tile 128x128, 8 warps (4m x 2n),
// warp tile m32 x n64, K-chunks of 64, single-fp16 A and W.
// 3-stage cp.async pipeline (prefetch distance 2), 32KB/stage = 96KB, 2 CTAs/SM.
// ---------------------------------------------------------------------------
#define OGS_AH 0
#define OGS_BH 16384
#define OG_STAGE 32768
#define OG_SMEM  98304

__global__ __launch_bounds__(256, 2) void gemm_mma(const float* __restrict__ bias,
                                                   float* __restrict__ out) {
    extern __shared__ char smp[];
    const uint32_t sb = smem_u32(smp);
    const int tid = threadIdx.x;
    const int w = tid >> 5, lane = tid & 31;
    const int wy = w >> 1, wx = w & 1;
    const int bm = blockIdx.y * 128, bn = blockIdx.x * 128;

    const __half* Ah = g_att_hi;
    const __half* Bh = g_w_hi;

    float acc[2][8][4];
    #pragma unroll
    for (int mi = 0; mi < 2; mi++)
        #pragma unroll
        for (int j = 0; j < 8; j++)
            #pragma unroll
            for (int rr = 0; rr < 4; rr++) acc[mi][j][rr] = 0.0f;

    // chunk loader: k=64 chunk -> Ah/Bh, 1024 16B-chunks each (128 rows x 8)
    auto issue_chunk = [&](int kc, uint32_t ss) {
        const int kw = kc * 64;
        #pragma unroll
        for (int i = 0; i < 4; i++) {
            int idx = tid + i * 256;          // 1024 slots: 128 rows x 8 chunks
            int row = idx >> 3, c = idx & 7;
            uint32_t sw = swz(row, c);
            cpa16(ss + OGS_AH + sw, Ah + (size_t)(bm + row) * EMB + kw + c * 8);
            cpa16(ss + OGS_BH + sw, Bh + (size_t)(bn + row) * EMB + kw + c * 8);
        }
        CP_COMMIT();
    };

    issue_chunk(0, sb);
    issue_chunk(1, sb + OG_STAGE);

    uint32_t stage = 0;                        // stage index of chunk kc
    for (int kc = 0; kc < 16; kc++) {
        const uint32_t ss = sb + stage * OG_STAGE;

        CP_WAIT1();            // chunk kc resident (kc+1 may be in flight)
        __syncthreads();       // all warps done with the stage being refilled

        if (kc + 2 < 16) {     // prefetch kc+2 into the stage freed by kc-1
            uint32_t stage2 = stage + 2; if (stage2 >= 3) stage2 -= 3;
            issue_chunk(kc + 2, sb + stage2 * OG_STAGE);
        }

        #pragma unroll
        for (int kk = 0; kk < 4; kk++) {
            uint32_t ah0[4], ah1[4];
            uint32_t ch = 2 * kk + (lane >> 4);
            ldsm4(ah0, ss + OGS_AH + swz(32 * wy + (lane & 15),      ch));
            ldsm4(ah1, ss + OGS_AH + swz(32 * wy + 16 + (lane & 15), ch));
            #pragma unroll
            for (int np = 0; np < 4; np++) {
                uint32_t bh4[4];
                uint32_t row = 64 * wx + 16 * np + (lane & 15);
                ldsm4(bh4, ss + OGS_BH + swz(row, ch));
                uint32_t b0h[2] = { bh4[0], bh4[2] }, b1h[2] = { bh4[1], bh4[3] };
                mma16816(acc[0][2 * np],     ah0, b0h);
                mma16816(acc[0][2 * np + 1], ah0, b1h);
                mma16816(acc[1][2 * np],     ah1, b0h);
                mma16816(acc[1][2 * np + 1], ah1, b1h);
            }
        }

        stage = (stage + 1 == 3) ? 0 : stage + 1;
    }

    #pragma unroll
    for (int mi = 0; mi < 2; mi++) {
        int r = bm + 32 * wy + 16 * mi + (lane >> 2);
        #pragma unroll
        for (int nt = 0; nt < 8; nt++) {
            int col = bn + 64 * wx + 8 * nt + 2 * (lane & 3);
            float bv0 = __ldg(bias + col), bv1 = __ldg(bias + col + 1);
            float2 v0, v1;
            v0.x = acc[mi][nt][0] + bv0; v0.y = acc[mi][nt][1] + bv1;
            v1.x = acc[mi][nt][2] + bv0; v1.y = acc[mi][nt][3] + bv1;
            *(float2*)(out + (size_t)r * EMB + col)       = v0;
            *(float2*)(out + (size_t)(r + 8) * EMB + col) = v1;
        }
    }
}

// ---------------------------------------------------------------------------
extern "C" void kernel_launch(void* const* d_in, const int* in_sizes, int n_in,
                              void* d_out, int out_size) {
    const float* x     = (const float*)d_in[0];   // [4,2048,1024]
    const float* theta = (const float*)d_in[1];   // [16,64]
    const float* w_out = (const float*)d_in[2];   // [1024,1024]
    const float* b_out = (const float*)d_in[3];   // [1024]
    float* out = (float*)d_out;                   // [4,2048,1024]

    cudaFuncSetAttribute(attn_mma, cudaFuncAttributeMaxDynamicSharedMemorySize, A_SMEM);
    cudaFuncSetAttribute(gemm_mma, cudaFuncAttributeMaxDynamicSharedMemorySize, OG_SMEM);

    qkv_kernel<<<(BATCH * SEQ * EMB) / 256, 256>>>(x, theta);
    wsplit_kernel<<<(EMB * EMB) / 256, 256>>>(w_out);
    attn_mma<<<BATCH * HEADS * (SEQ / 128), 256, A_SMEM>>>();
    dim3 ggrid(EMB / 128, (BATCH * SEQ) / 128);
    gemm_mma<<<ggrid, 256, OG_SMEM>>>(b_out, out);
}